// round 11
// baseline (speedup 1.0000x reference)
#include <cuda_runtime.h>
#include <cuda_bf16.h>
#include <math.h>
#include <cstdint>

// ---- problem constants ----
#define BB   2
#define TT   2048
#define DD   2048
#define NH   8
#define NKV  4
#define HD   256
#define SC   2048
#define WIN  512
#define GRP  (NH / NKV)   // 2
#define MM   (BB * TT)    // 4096

// ---- device scratch ----
__device__ float g_qkv[(size_t)MM * 4096];              // fused projection output (fp32)
__device__ float2 g_rope[(size_t)MM * 128];             // per-(row, i) sin/cos

__device__ __nv_bfloat16 g_xhi[(size_t)MM * DD], g_xlo[(size_t)MM * DD];
__device__ __nv_bfloat16 g_ahi[(size_t)MM * NH * HD], g_alo[(size_t)MM * NH * HD];

// attention operand caches, bf16 hi/lo
__device__ __nv_bfloat16 g_qhi[(size_t)BB * NH * TT * HD], g_qlo[(size_t)BB * NH * TT * HD];
__device__ __nv_bfloat16 g_khi[(size_t)BB * NKV * SC * HD], g_klo[(size_t)BB * NKV * SC * HD];
__device__ __nv_bfloat16 g_vthi[(size_t)BB * NKV * HD * SC], g_vtlo[(size_t)BB * NKV * HD * SC];

#define WQ_OFF 0
#define WK_OFF ((size_t)DD * DD)
#define WV_OFF (WK_OFF + (size_t)DD * NKV * HD)
#define WO_OFF (WV_OFF + (size_t)DD * NKV * HD)
#define W_TOT  (WO_OFF + (size_t)NH * HD * DD)
__device__ __nv_bfloat16 g_wthi[W_TOT], g_wtlo[W_TOT];  // weights transposed [N,K], hi/lo

// ============================================================
// helpers
// ============================================================
__device__ __forceinline__ uint32_t s2u(const void* p) {
    uint32_t a;
    asm("{ .reg .u64 t; cvta.to.shared.u64 t, %1; cvt.u32.u64 %0, t; }" : "=r"(a) : "l"(p));
    return a;
}
__device__ __forceinline__ void cpasync16(uint32_t saddr, const void* gaddr) {
    asm volatile("cp.async.cg.shared.global [%0], [%1], 16;" :: "r"(saddr), "l"(gaddr));
}
__device__ __forceinline__ void cp_commit() {
    asm volatile("cp.async.commit_group;" ::: "memory");
}
__device__ __forceinline__ void cp_wait1() {
    asm volatile("cp.async.wait_group 1;" ::: "memory");
}
__device__ __forceinline__ void cp_wait0() {
    asm volatile("cp.async.wait_group 0;" ::: "memory");
}
__device__ __forceinline__ void ldm4(uint32_t* d, uint32_t addr) {
    asm volatile("ldmatrix.sync.aligned.m8n8.x4.shared.b16 {%0,%1,%2,%3}, [%4];"
                 : "=r"(d[0]), "=r"(d[1]), "=r"(d[2]), "=r"(d[3]) : "r"(addr));
}
__device__ __forceinline__ void mma16816(float* c, const uint32_t* a, uint32_t b0, uint32_t b1) {
    asm volatile("mma.sync.aligned.m16n8k16.row.col.f32.bf16.bf16.f32 "
                 "{%0,%1,%2,%3}, {%4,%5,%6,%7}, {%8,%9}, {%0,%1,%2,%3};"
                 : "+f"(c[0]), "+f"(c[1]), "+f"(c[2]), "+f"(c[3])
                 : "r"(a[0]), "r"(a[1]), "r"(a[2]), "r"(a[3]), "r"(b0), "r"(b1));
}
__device__ __forceinline__ __nv_bfloat162 split_pack_hi(float a, float b,
                                                        __nv_bfloat162* lo) {
    __nv_bfloat16 ha = __float2bfloat16(a), hb = __float2bfloat16(b);
    *lo = __halves2bfloat162(__float2bfloat16(a - __bfloat162float(ha)),
                             __float2bfloat16(b - __bfloat162float(hb)));
    return __halves2bfloat162(ha, hb);
}

// ============================================================
// convert: fp32 -> (hi, lo) bf16 pair, vectorized x4
// ============================================================
__global__ void __launch_bounds__(256) convert_split(const float4* __restrict__ src,
                                                     __nv_bfloat162* __restrict__ hi,
                                                     __nv_bfloat162* __restrict__ lo,
                                                     int n4)
{
    int i = blockIdx.x * 256 + threadIdx.x;
    if (i >= n4) return;
    float4 v = src[i];
    __nv_bfloat162 l0, l1;
    __nv_bfloat162 h0 = split_pack_hi(v.x, v.y, &l0);
    __nv_bfloat162 h1 = split_pack_hi(v.z, v.w, &l1);
    hi[2 * i] = h0; hi[2 * i + 1] = h1;
    lo[2 * i] = l0; lo[2 * i + 1] = l1;
}

// ============================================================
// transpose + split: W[K,N] fp32 -> Wt_hi/lo [N,K] bf16
// ============================================================
__global__ void __launch_bounds__(256) transpose_split(const float* __restrict__ W,
                                                       __nv_bfloat16* __restrict__ Th,
                                                       __nv_bfloat16* __restrict__ Tl,
                                                       int K, int N)
{
    __shared__ float s[32][33];
    int n0 = blockIdx.x * 32, k0 = blockIdx.y * 32;
    for (int i = threadIdx.y; i < 32; i += 8)
        s[i][threadIdx.x] = W[(size_t)(k0 + i) * N + n0 + threadIdx.x];
    __syncthreads();
    for (int i = threadIdx.y; i < 32; i += 8) {
        float v = s[threadIdx.x][i];
        __nv_bfloat16 h = __float2bfloat16(v);
        size_t o = (size_t)(n0 + i) * K + k0 + threadIdx.x;
        Th[o] = h;
        Tl[o] = __float2bfloat16(v - __bfloat162float(h));
    }
}

// ============================================================
// RoPE sin/cos table: per (row, i<128)
// ============================================================
__global__ void __launch_bounds__(256) rope_table(const int* __restrict__ segpos)
{
    int idx = blockIdx.x * 256 + threadIdx.x;       // MM*128 total
    int row = idx >> 7, i = idx & 127;
    float pos = (float)segpos[row];
    float ts  = exp2f((float)i * (13.287712379549449f / 128.0f));
    float sv, cv;
    sincosf(pos / ts, &sv, &cv);
    g_rope[idx] = make_float2(sv, cv);
}

// ============================================================
// V transpose + split
// ============================================================
__global__ void __launch_bounds__(256) vtrans_kernel(const int* __restrict__ curind)
{
    __shared__ float s[32][33];
    int t0 = blockIdx.x * 32, d0 = blockIdx.y * 32;
    int bkv = blockIdx.z;
    int b = bkv / NKV, kv = bkv - b * NKV;
    int tx = threadIdx.x, ty = threadIdx.y;
    for (int i = ty; i < 32; i += 8)
        s[i][tx] = g_qkv[(size_t)(b * TT + t0 + i) * 4096 + 3072 + kv * HD + d0 + tx];
    __syncthreads();
    int s0 = curind[0] + t0;
    for (int i = ty; i < 32; i += 8) {
        float v = s[tx][i];
        __nv_bfloat16 h = __float2bfloat16(v);
        size_t o = ((size_t)bkv * HD + d0 + i) * SC + s0 + tx;
        g_vthi[o] = h;
        g_vtlo[o] = __float2bfloat16(v - __bfloat162float(h));
    }
}

// ============================================================
// HMMA GEMM (bf16 x3 split), 128(M) x 256(N) CTA tile, BK=64,
// 2-stage cp.async double buffer, 8 warps in 2m x 4n, warp 64x64.
// C[M,N] = (Ahi+Alo)[M,K] @ (Bhi+Blo)[N,K]^T
// ============================================================
#define ST_AHI 0
#define ST_ALO 16384
#define ST_BHI 32768                 // B hi: 256 x 128B = 32768
#define ST_BLO 65536
#define STAGE_BYTES 98304            // 96 KB
#define GEMM_SMEM   (2 * STAGE_BYTES)  // 196608

__device__ __forceinline__ void load_stage(uint32_t sbase,
    const __nv_bfloat16* __restrict__ Ahi, const __nv_bfloat16* __restrict__ Alo,
    const __nv_bfloat16* __restrict__ Bhi, const __nv_bfloat16* __restrict__ Blo,
    int Kdim, int m0, int n0, int k0, int tid)
{
    // A: 128 rows x 8 x 16B ; hi + lo
#pragma unroll
    for (int ii = 0; ii < 4; ii++) {
        int i = tid + ii * 256;
        int r = i >> 3, c = i & 7;
        uint32_t so = (uint32_t)(r * 128 + ((c ^ (r & 7)) << 4));
        size_t go = (size_t)(m0 + r) * Kdim + k0 + c * 8;
        cpasync16(sbase + ST_AHI + so, Ahi + go);
        cpasync16(sbase + ST_ALO + so, Alo + go);
    }
    // B: 256 rows x 8 x 16B ; hi + lo
#pragma unroll
    for (int ii = 0; ii < 8; ii++) {
        int i = tid + ii * 256;
        int r = i >> 3, c = i & 7;
        uint32_t so = (uint32_t)(r * 128 + ((c ^ (r & 7)) << 4));
        size_t go = (size_t)(n0 + r) * Kdim + k0 + c * 8;
        cpasync16(sbase + ST_BHI + so, Bhi + go);
        cpasync16(sbase + ST_BLO + so, Blo + go);
    }
}

__global__ void __launch_bounds__(256, 1) gemm_bf16x3(
    const __nv_bfloat16* __restrict__ Ahi, const __nv_bfloat16* __restrict__ Alo,
    const __nv_bfloat16* __restrict__ Bhi, const __nv_bfloat16* __restrict__ Blo,
    float* __restrict__ C, int Ndim, int Kdim)
{
    extern __shared__ __align__(128) char smem[];
    const uint32_t sb = s2u(smem);
    const int tid  = threadIdx.x;
    const int wid  = tid >> 5;
    const int lane = tid & 31;
    const int wm   = wid >> 2;          // 0..1 -> M offset wm*64
    const int wn   = wid & 3;           // 0..3 -> N offset wn*64
    const int m0   = blockIdx.y * 128;
    const int n0   = blockIdx.x * 256;

    const int lrow = lane & 15;
    const int lkc  = lane >> 4;

    int arow[4], brow[4];
#pragma unroll
    for (int mt = 0; mt < 4; mt++) arow[mt] = wm * 64 + mt * 16 + lrow;
#pragma unroll
    for (int nt = 0; nt < 4; nt++) brow[nt] = wn * 64 + nt * 16 + lrow;

    float acc[4][4][2][4];               // 128 regs
#pragma unroll
    for (int mt = 0; mt < 4; mt++)
#pragma unroll
        for (int nt = 0; nt < 4; nt++)
#pragma unroll
            for (int h = 0; h < 2; h++)
#pragma unroll
                for (int r = 0; r < 4; r++) acc[mt][nt][h][r] = 0.f;

    const int nk = Kdim >> 6;

    load_stage(sb, Ahi, Alo, Bhi, Blo, Kdim, m0, n0, 0, tid);
    cp_commit();

    for (int c = 0; c < nk; c++) {
        if (c + 1 < nk) {
            load_stage(sb + ((c + 1) & 1) * STAGE_BYTES, Ahi, Alo, Bhi, Blo,
                       Kdim, m0, n0, (c + 1) << 6, tid);
            cp_commit();
            cp_wait1();
        } else {
            cp_wait0();
        }
        __syncthreads();

        const uint32_t st = sb + (c & 1) * STAGE_BYTES;

#pragma unroll
        for (int ks = 0; ks < 4; ks++) {
            const int chunk = ks * 2 + lkc;
            uint32_t af[4][4], bf[4][4], af2[4][4];

            // --- term 1: hi*hi ---
#pragma unroll
            for (int mt = 0; mt < 4; mt++) {
                uint32_t off = (uint32_t)(arow[mt] * 128 + ((chunk ^ (arow[mt] & 7)) << 4));
                ldm4(af[mt], st + ST_AHI + off);
            }
#pragma unroll
            for (int nt = 0; nt < 4; nt++) {
                uint32_t off = (uint32_t)(brow[nt] * 128 + ((chunk ^ (brow[nt] & 7)) << 4));
                ldm4(bf[nt], st + ST_BHI + off);
            }
#pragma unroll
            for (int mt = 0; mt < 4; mt++)
#pragma unroll
                for (int nt = 0; nt < 4; nt++)
#pragma unroll
                    for (int h = 0; h < 2; h++)
                        mma16816(acc[mt][nt][h], af[mt], bf[nt][h], bf[nt][h + 2]);

            // --- term 2: lo*hi (load A lo; B hi still resident) ---
#pragma unroll
            for (int mt = 0; mt < 4; mt++) {
                uint32_t off = (uint32_t)(arow[mt] * 128 + ((chunk ^ (arow[mt] & 7)) << 4));
                ldm4(af2[mt], st + ST_ALO + off);
            }
#pragma unroll
            for (int mt = 0; mt < 4; mt++)
#pragma unroll
                for (int nt = 0; nt < 4; nt++)
#pragma unroll
                    for (int h = 0; h < 2; h++)
                        mma16816(acc[mt][nt][h], af2[mt], bf[nt][h], bf[nt][h + 2]);

            // --- term 3: hi*lo (B lo overwrites B hi regs) ---
#pragma unroll
            for (int nt = 0; nt < 4; nt++) {
                uint32_t off = (uint32_t)(brow[nt] * 128 + ((chunk ^ (brow[nt] & 7)) << 4));
                ldm4(bf[nt], st + ST_BLO + off);
            }
#pragma unroll
            for (int mt = 0; mt < 4; mt++)
#pragma unroll
                for (int nt = 0; nt < 4; nt++)
#pragma unroll
                    for (int h = 0; h < 2; h++)
                        mma16816(acc[mt][nt][h], af[mt], bf[nt][h], bf[nt][h + 2]);
        }
    }

    const int qr = lane >> 2;
    const int qc = lane & 3;
#pragma unroll
    for (int mt = 0; mt < 4; mt++) {
#pragma unroll
        for (int nt = 0; nt < 4; nt++) {
#pragma unroll
            for (int h = 0; h < 2; h++) {
                int row = m0 + wm * 64 + mt * 16 + qr;
                int col = n0 + wn * 64 + nt * 16 + h * 8 + qc * 2;
                float* d = acc[mt][nt][h];
                *(float2*)(C + (size_t)row * Ndim + col)       = make_float2(d[0], d[1]);
                *(float2*)(C + (size_t)(row + 8) * Ndim + col) = make_float2(d[2], d[3]);
            }
        }
    }
}

// ============================================================
// RMSNorm + RoPE (table) -> bf16 hi/lo operand caches
// ============================================================
__global__ void __launch_bounds__(256) normrope_kernel(const int* __restrict__ segpos,
                                                       const int* __restrict__ curind,
                                                       const float* __restrict__ qns,
                                                       const float* __restrict__ kns)
{
    const int row  = blockIdx.x;
    const int slot = blockIdx.y;
    const int d    = threadIdx.x;
    const int b    = row / TT;
    const int t    = row - b * TT;

    const float* src;
    const float* sc;
    if (slot < NH) {
        src = g_qkv + (size_t)row * 4096 + slot * HD;
        sc  = qns;
    } else {
        src = g_qkv + (size_t)row * 4096 + 2048 + (slot - NH) * HD;
        sc  = kns;
    }

    float v  = src[d];
    float ss = v * v;
#pragma unroll
    for (int o = 16; o > 0; o >>= 1) ss += __shfl_xor_sync(0xffffffffu, ss, o);

    __shared__ float wsum[8];
    __shared__ float s_n[HD];
    __shared__ float s_r;
    if ((d & 31) == 0) wsum[d >> 5] = ss;
    __syncthreads();
    if (d == 0) {
        float tot = 0.f;
#pragma unroll
        for (int w = 0; w < 8; w++) tot += wsum[w];
        s_r = rsqrtf(tot * (1.0f / HD) + 1e-6f);
    }
    __syncthreads();

    float n = v * s_r * (1.0f + sc[d]);
    s_n[d] = n;
    __syncthreads();

    float2 sc2 = g_rope[(size_t)row * 128 + (d & 127)];
    float outv = (d < 128) ? (n * sc2.y - s_n[d + 128] * sc2.x)
                           : (n * sc2.y + s_n[d - 128] * sc2.x);

    if (slot < NH) {
        outv *= 0.0625f;   // fold HD^-1/2
        size_t o = ((size_t)(b * NH + slot) * TT + t) * HD + d;
        __nv_bfloat16 h = __float2bfloat16(outv);
        g_qhi[o] = h;
        g_qlo[o] = __float2bfloat16(outv - __bfloat162float(h));
    } else {
        int kv = slot - NH;
        int ct = curind[0] + t;
        size_t o = ((size_t)(b * NKV + kv) * SC + ct) * HD + d;
        __nv_bfloat16 h = __float2bfloat16(outv);
        g_khi[o] = h;
        g_klo[o] = __float2bfloat16(outv - __bfloat162float(h));
    }
}

// ============================================================
// HMMA windowed attention, double-buffered K/V chunk pipeline.
// Block: 64 queries x one (b,h); 256 threads = 8 warps.
// ============================================================
#define ATQ 64
#define ACK 32
// smem byte offsets
#define SQH 0                          // Q hi: 4 subtiles x 64 x 128B = 32768
#define SQL 32768
#define SKB0 65536                     // K stage: hi 16384 + lo 16384; x2 stages
#define SK_STRIDE 32768
#define SVB0 131072                    // V stage: hi 20480 + lo 20480; x2 stages
#define SV_STRIDE 40960
#define SPH 212992                     // P hi: 64 x 80B
#define SPL 218112
#define SPS 223232                     // psum[2][64] fp32
#define ATTN_SMEM 223744

__device__ __forceinline__ float capexp(float a, int pos, int s) {
    float e = __expf(a * 0.04f);                       // e^{2a/50}
    float t = 50.0f * __fdividef(e - 1.0f, e + 1.0f);  // 50*tanh(a/50)
    bool valid = (s <= pos) && (pos - s < WIN);
    return valid ? __expf(t) : 0.0f;
}

__device__ __forceinline__ void attn_load_chunk(char* sm, uint32_t sb, int buf,
                                                int s0, int bkv, int tid)
{
    const uint32_t kb = sb + SKB0 + buf * SK_STRIDE;
    const uint32_t ko = SKB0 + buf * SK_STRIDE;
    for (int i = tid; i < 32 * 32; i += 256) {
        int r = i >> 5, c = i & 31;
        int s = s0 + r;
        int sub = c >> 3, cc = c & 7;
        uint32_t so = (uint32_t)(sub * 4096 + r * 128 + ((cc ^ (r & 7)) << 4));
        if (s < SC) {
            size_t go = ((size_t)bkv * SC + s) * HD + c * 8;
            cpasync16(kb + so, g_khi + go);
            cpasync16(kb + 16384 + so, g_klo + go);
        } else {
            *(uint4*)(sm + ko + so)         = make_uint4(0, 0, 0, 0);
            *(uint4*)(sm + ko + 16384 + so) = make_uint4(0, 0, 0, 0);
        }
    }
    const uint32_t vb = sb + SVB0 + buf * SV_STRIDE;
    const uint32_t vo = SVB0 + buf * SV_STRIDE;
    for (int i = tid; i < 256 * 4; i += 256) {
        int dd = i >> 2, c = i & 3;
        uint32_t so = (uint32_t)(dd * 80 + c * 16);
        if (s0 + c * 8 + 7 < SC) {
            size_t go = ((size_t)bkv * HD + dd) * SC + s0 + c * 8;
            cpasync16(vb + so, g_vthi + go);
            cpasync16(vb + 20480 + so, g_vtlo + go);
        } else {
            *(uint4*)(sm + vo + so)         = make_uint4(0, 0, 0, 0);
            *(uint4*)(sm + vo + 20480 + so) = make_uint4(0, 0, 0, 0);
        }
    }
}

__global__ void __launch_bounds__(256) attn_mma(const int* __restrict__ segpos)
{
    extern __shared__ __align__(128) char sm[];
    const uint32_t sb = s2u(sm);
    const int tid  = threadIdx.x;
    const int wid  = tid >> 5;
    const int lane = tid & 31;
    const int t0   = blockIdx.x * ATQ;
    const int head = blockIdx.y;
    const int b    = blockIdx.z;
    const int kv   = head / GRP;
    const int bkv  = b * NKV + kv;
    const int wm   = wid >> 1;
    const int wh   = wid & 1;
    const int lrow = lane & 15;
    const int lkc  = lane >> 4;
    const int qr   = lane >> 2;
    const int qc   = lane & 3;

    float* psum = (float*)(sm + SPS);

    // window bounds (direct global reads; same addr across warp -> broadcast)
    int minp, maxp;
    {
        const int* sp = segpos + b * TT + t0;
        minp = sp[0]; maxp = sp[0];
#pragma unroll 8
        for (int i = 1; i < ATQ; i++) {
            int p = sp[i];
            minp = min(minp, p);
            maxp = max(maxp, p);
        }
    }
    const int smin = max(0, minp - (WIN - 1)) & ~31;
    const int smax = min(SC - 1, maxp);
    const int nchunks = ((smax - smin) >> 5) + 1;

    const int myp0 = segpos[b * TT + t0 + wm * 16 + qr];
    const int myp1 = segpos[b * TT + t0 + wm * 16 + qr + 8];

    if (tid < 2 * ATQ) psum[tid] = 0.f;

    // prologue: Q tile + chunk 0  (one commit group)
    {
        const __nv_bfloat16* gh = g_qhi + ((size_t)(b * NH + head) * TT + t0) * HD;
        const __nv_bfloat16* gl = g_qlo + ((size_t)(b * NH + head) * TT + t0) * HD;
        for (int i = tid; i < ATQ * 32; i += 256) {
            int r = i >> 5, c = i & 31;
            int sub = c >> 3, cc = c & 7;
            uint32_t so = (uint32_t)(sub * 8192 + r * 128 + ((cc ^ (r & 7)) << 4));
            cpasync16(sb + SQH + so, gh + (size_t)r * HD + c * 8);
            cpasync16(sb + SQL + so, gl + (size_t)r * HD + c * 8);
        }
        attn_load_chunk(sm, sb, 0, smin, bkv, tid);
    }
    cp_commit();

    float oacc[16][4];
#pragma unroll
    for (int i = 0; i < 16; i++)
#pragma unroll
        for (int r = 0; r < 4; r++) oacc[i][r] = 0.f;

    for (int ci = 0; ci < nchunks; ci++) {
        const int s0 = smin + ci * ACK;
        __syncthreads();                       // prev PV done (protects buf ci+1 overwrite)
        if (ci + 1 < nchunks)
            attn_load_chunk(sm, sb, (ci + 1) & 1, s0 + ACK, bkv, tid);
        cp_commit();
        cp_wait1();                            // chunk ci (and Q on ci=0) ready
        __syncthreads();

        const uint32_t kb = sb + SKB0 + (ci & 1) * SK_STRIDE;
        const uint32_t vb = sb + SVB0 + (ci & 1) * SV_STRIDE;

        // ---- QK^T : m16 x n16 per warp, k = 256 ----
        float sacc[2][4];
#pragma unroll
        for (int hh = 0; hh < 2; hh++)
#pragma unroll
            for (int r = 0; r < 4; r++) sacc[hh][r] = 0.f;

        const int arow = wm * 16 + lrow;
        const int brow = wh * 16 + lrow;
#pragma unroll
        for (int ks = 0; ks < 16; ks++) {
            int sub = ks >> 2, cc = (ks & 3) * 2 + lkc;
            uint32_t ao = (uint32_t)(sub * 8192 + arow * 128 + ((cc ^ (arow & 7)) << 4));
            uint32_t bo = (uint32_t)(sub * 4096 + brow * 128 + ((cc ^ (brow & 7)) << 4));
            uint32_t ah[4], al[4], bh[4], bl[4];
            ldm4(ah, sb + SQH + ao);
            ldm4(al, sb + SQL + ao);
            ldm4(bh, kb + bo);
            ldm4(bl, kb + 16384 + bo);
#pragma unroll
            for (int hh = 0; hh < 2; hh++) mma16816(sacc[hh], ah, bh[hh], bh[hh + 2]);
#pragma unroll
            for (int hh = 0; hh < 2; hh++) mma16816(sacc[hh], ah, bl[hh], bl[hh + 2]);
#pragma unroll
            for (int hh = 0; hh < 2; hh++) mma16816(sacc[hh], al, bh[hh], bh[hh + 2]);
        }

        // ---- softcap + mask + exp; write P hi/lo; partial row sums ----
        float rs0 = 0.f, rs1 = 0.f;
#pragma unroll
        for (int hh = 0; hh < 2; hh++) {
            int colL = wh * 16 + hh * 8 + 2 * qc;
            int colG = s0 + colL;
            float p00 = capexp(sacc[hh][0], myp0, colG);
            float p01 = capexp(sacc[hh][1], myp0, colG + 1);
            float p10 = capexp(sacc[hh][2], myp1, colG);
            float p11 = capexp(sacc[hh][3], myp1, colG + 1);
            rs0 += p00 + p01;
            rs1 += p10 + p11;
            __nv_bfloat162 lo0, lo1;
            __nv_bfloat162 hi0 = split_pack_hi(p00, p01, &lo0);
            __nv_bfloat162 hi1 = split_pack_hi(p10, p11, &lo1);
            int r0 = wm * 16 + qr;
            uint32_t o0 = (uint32_t)(r0 * 80 + colL * 2);
            uint32_t o1 = o0 + 8 * 80;
            *(__nv_bfloat162*)(sm + SPH + o0) = hi0;
            *(__nv_bfloat162*)(sm + SPL + o0) = lo0;
            *(__nv_bfloat162*)(sm + SPH + o1) = hi1;
            *(__nv_bfloat162*)(sm + SPL + o1) = lo1;
        }
        rs0 += __shfl_xor_sync(0xffffffffu, rs0, 1);
        rs0 += __shfl_xor_sync(0xffffffffu, rs0, 2);
        rs1 += __shfl_xor_sync(0xffffffffu, rs1, 1);
        rs1 += __shfl_xor_sync(0xffffffffu, rs1, 2);
        if (qc == 0) {
            psum[wh * 64 + wm * 16 + qr]     += rs0;
            psum[wh * 64 + wm * 16 + qr + 8] += rs1;
        }
        __syncthreads();

        // ---- P @ V : m16 x d128 per warp, k = 32 ----
        const int prow = wm * 16 + lrow;
#pragma unroll
        for (int ks2 = 0; ks2 < 2; ks2++) {
            uint32_t po = (uint32_t)(prow * 80 + ((ks2 * 2 + lkc) << 4));
            uint32_t ph[4], pl[4];
            ldm4(ph, sb + SPH + po);
            ldm4(pl, sb + SPL + po);
            uint32_t vh4[8][4], vl4[8][4];
#pragma unroll
            for (int nt = 0; nt < 8; nt++) {
                int vrow = wh * 128 + nt * 16 + lrow;
                uint32_t vo = (uint32_t)(vrow * 80 + ((ks2 * 2 + lkc) << 4));
                ldm4(vh4[nt], vb + vo);
                ldm4(vl4[nt], vb + 20480 + vo);
            }
#pragma unroll
            for (int nt = 0; nt < 8; nt++)
#pragma unroll
                for (int hh = 0; hh < 2; hh++)
                    mma16816(oacc[nt * 2 + hh], ph, vh4[nt][hh], vh4[nt][hh + 2]);
#pragma unroll
            for (int nt = 0; nt < 8; nt++)
#pragma unroll
                for (int hh = 0; hh < 2; hh++)
                    mma16816(oacc[nt * 2 + hh], ph, vl4[nt][hh], vl4[nt][hh + 2]);
#pragma unroll
            for (int nt = 0; nt < 8; nt++)
#pragma unroll
                for (int hh = 0; hh < 2; hh++)
                    mma16816(oacc[nt * 2 + hh], pl, vh4[nt][hh], vh4[nt][hh + 2]);
        }
    }

    // ---- epilogue: divide by row sums, write bf16 hi/lo for O-proj ----
    const int r0 = wm * 16 + qr;
    const float inv0 = __fdividef(1.0f, psum[r0] + psum[64 + r0]);
    const float inv1 = __fdividef(1.0f, psum[r0 + 8] + psum[64 + r0 + 8]);
    const size_t tok0 = (size_t)(b * TT + t0 + r0);
#pragma unroll
    for (int nt = 0; nt < 8; nt++) {
#pragma unroll
        for (int hh = 0; hh < 2; hh++) {
            int col = head * HD + wh * 128 + nt * 16 + hh * 8 + 2 * qc;
            float* d = oacc[nt * 2 + hh];
            __nv_bfloat162 lo0, lo1;
            __nv_bfloat162 hi0 = split_pack_hi(d[0] * inv0, d[1] * inv0, &lo0);
            __nv_bfloat162 hi1 = split_pack_hi(d[2] * inv1, d[3] * inv1, &lo1);
            *(__nv_bfloat162*)(g_ahi + tok0 * 2048 + col)       = hi0;
            *(__nv_bfloat162*)(g_alo + tok0 * 2048 + col)       = lo0;
            *(__nv_bfloat162*)(g_ahi + (tok0 + 8) * 2048 + col) = hi1;
            *(__nv_bfloat162*)(g_alo + (tok0 + 8) * 2048 + col) = lo1;
        }
    }
}

// ============================================================
// Launch
// ============================================================
extern "C" void kernel_launch(void* const* d_in, const int* in_sizes, int n_in,
                              void* d_out, int out_size)
{
    const float* x      = (const float*)d_in[0];
    const int*   segpos = (const int*)  d_in[1];
    const int*   curind = (const int*)  d_in[2];
    const float* wq     = (const float*)d_in[3];
    const float* wk     = (const float*)d_in[4];
    const float* wv     = (const float*)d_in[5];
    const float* wo     = (const float*)d_in[6];
    const float* qns    = (const float*)d_in[7];
    const float* kns    = (const float*)d_in[8];
    float* out = (float*)d_out;

    float* gqkv;
    __nv_bfloat16 *xhi, *xlo, *ahi, *alo, *wthi, *wtlo;
    cudaGetSymbolAddress((void**)&gqkv, g_qkv);
    cudaGetSymbolAddress((void**)&xhi,  g_xhi);
    cudaGetSymbolAddress((void**)&xlo,  g_xlo);
    cudaGetSymbolAddress((void**)&ahi,  g_ahi);
    cudaGetSymbolAddress((void**)&alo,  g_alo);
    cudaGetSymbolAddress((void**)&wthi, g_wthi);
    cudaGetSymbolAddress((void**)&wtlo, g_wtlo);

    // 1) split x into bf16 hi/lo ; rope table
    {
        int n4 = (MM * DD) / 4;
        convert_split<<<n4 / 256, 256>>>((const float4*)x,
                                         (__nv_bfloat162*)xhi, (__nv_bfloat162*)xlo, n4);
    }
    rope_table<<<(MM * 128) / 256, 256>>>(segpos);

    // 2) transpose + split weights
    transpose_split<<<dim3(DD / 32, DD / 32), dim3(32, 8)>>>(wq, wthi + WQ_OFF, wtlo + WQ_OFF, DD, DD);
    transpose_split<<<dim3((NKV * HD) / 32, DD / 32), dim3(32, 8)>>>(wk, wthi + WK_OFF, wtlo + WK_OFF, DD, NKV * HD);
    transpose_split<<<dim3((NKV * HD) / 32, DD / 32), dim3(32, 8)>>>(wv, wthi + WV_OFF, wtlo + WV_OFF, DD, NKV * HD);
    transpose_split<<<dim3(DD / 32, DD / 32), dim3(32, 8)>>>(wo, wthi + WO_OFF, wtlo + WO_OFF, NH * HD, DD);

    // 3) fused QKV projection: [4096,2048] @ [2048,4096]^T(layout)
    cudaFuncSetAttribute(gemm_bf16x3, cudaFuncAttributeMaxDynamicSharedMemorySize, GEMM_SMEM);
    gemm_bf16x3<<<dim3(4096 / 256, MM / 128), 256, GEMM_SMEM>>>(
        xhi, xlo, wthi, wtlo, gqkv, 4096, DD);

    // 4) norm + rope -> bf16 hi/lo q + k-cache ; v transpose -> vt cache
    normrope_kernel<<<dim3(MM, NH + NKV), 256>>>(segpos, curind, qns, kns);
    vtrans_kernel<<<dim3(TT / 32, HD / 32, BB * NKV), dim3(32, 8)>>>(curind);

    // 5) HMMA attention -> g_ahi/g_alo
    cudaFuncSetAttribute(attn_mma, cudaFuncAttributeMaxDynamicSharedMemorySize, ATTN_SMEM);
    attn_mma<<<dim3(TT / ATQ, NH, BB), 256, ATTN_SMEM>>>(segpos);

    // 6) output projection -> d_out
    gemm_bf16x3<<<dim3(DD / 256, MM / 128), 256, GEMM_SMEM>>>(
        ahi, alo, wthi + WO_OFF, wtlo + WO_OFF, out, DD, NH * HD);
}

// round 12
// speedup vs baseline: 1.0408x; 1.0408x over previous
#include <cuda_runtime.h>
#include <cuda_bf16.h>
#include <math.h>
#include <cstdint>

// ---- problem constants ----
#define BB   2
#define TT   2048
#define DD   2048
#define NH   8
#define NKV  4
#define HD   256
#define SC   2048
#define WIN  512
#define GRP  (NH / NKV)   // 2
#define MM   (BB * TT)    // 4096

// ---- device scratch ----
__device__ float g_qkv[(size_t)MM * 4096];              // fused projection output (fp32)
__device__ float2 g_rope[(size_t)MM * 128];             // per-(row, i) sin/cos

__device__ __nv_bfloat16 g_xhi[(size_t)MM * DD], g_xlo[(size_t)MM * DD];
__device__ __nv_bfloat16 g_ahi[(size_t)MM * NH * HD], g_alo[(size_t)MM * NH * HD];

// attention operand caches, bf16 hi/lo
__device__ __nv_bfloat16 g_qhi[(size_t)BB * NH * TT * HD], g_qlo[(size_t)BB * NH * TT * HD];
__device__ __nv_bfloat16 g_khi[(size_t)BB * NKV * SC * HD], g_klo[(size_t)BB * NKV * SC * HD];
__device__ __nv_bfloat16 g_vthi[(size_t)BB * NKV * HD * SC], g_vtlo[(size_t)BB * NKV * HD * SC];

#define WQ_OFF 0
#define WK_OFF ((size_t)DD * DD)
#define WV_OFF (WK_OFF + (size_t)DD * NKV * HD)
#define WO_OFF (WV_OFF + (size_t)DD * NKV * HD)
#define W_TOT  (WO_OFF + (size_t)NH * HD * DD)
__device__ __nv_bfloat16 g_wthi[W_TOT], g_wtlo[W_TOT];  // weights transposed [N,K], hi/lo

// ============================================================
// helpers
// ============================================================
__device__ __forceinline__ uint32_t s2u(const void* p) {
    uint32_t a;
    asm("{ .reg .u64 t; cvta.to.shared.u64 t, %1; cvt.u32.u64 %0, t; }" : "=r"(a) : "l"(p));
    return a;
}
__device__ __forceinline__ void cpasync16(uint32_t saddr, const void* gaddr) {
    asm volatile("cp.async.cg.shared.global [%0], [%1], 16;" :: "r"(saddr), "l"(gaddr));
}
__device__ __forceinline__ void cp_commit() {
    asm volatile("cp.async.commit_group;" ::: "memory");
}
__device__ __forceinline__ void cp_wait1() {
    asm volatile("cp.async.wait_group 1;" ::: "memory");
}
__device__ __forceinline__ void cp_wait0() {
    asm volatile("cp.async.wait_group 0;" ::: "memory");
}
__device__ __forceinline__ void ldm4(uint32_t* d, uint32_t addr) {
    asm volatile("ldmatrix.sync.aligned.m8n8.x4.shared.b16 {%0,%1,%2,%3}, [%4];"
                 : "=r"(d[0]), "=r"(d[1]), "=r"(d[2]), "=r"(d[3]) : "r"(addr));
}
__device__ __forceinline__ void mma16816(float* c, const uint32_t* a, uint32_t b0, uint32_t b1) {
    asm volatile("mma.sync.aligned.m16n8k16.row.col.f32.bf16.bf16.f32 "
                 "{%0,%1,%2,%3}, {%4,%5,%6,%7}, {%8,%9}, {%0,%1,%2,%3};"
                 : "+f"(c[0]), "+f"(c[1]), "+f"(c[2]), "+f"(c[3])
                 : "r"(a[0]), "r"(a[1]), "r"(a[2]), "r"(a[3]), "r"(b0), "r"(b1));
}
__device__ __forceinline__ __nv_bfloat162 split_pack_hi(float a, float b,
                                                        __nv_bfloat162* lo) {
    __nv_bfloat16 ha = __float2bfloat16(a), hb = __float2bfloat16(b);
    *lo = __halves2bfloat162(__float2bfloat16(a - __bfloat162float(ha)),
                             __float2bfloat16(b - __bfloat162float(hb)));
    return __halves2bfloat162(ha, hb);
}

// ============================================================
// convert: fp32 -> (hi, lo) bf16 pair, vectorized x4
// ============================================================
__global__ void __launch_bounds__(256) convert_split(const float4* __restrict__ src,
                                                     __nv_bfloat162* __restrict__ hi,
                                                     __nv_bfloat162* __restrict__ lo,
                                                     int n4)
{
    int i = blockIdx.x * 256 + threadIdx.x;
    if (i >= n4) return;
    float4 v = src[i];
    __nv_bfloat162 l0, l1;
    __nv_bfloat162 h0 = split_pack_hi(v.x, v.y, &l0);
    __nv_bfloat162 h1 = split_pack_hi(v.z, v.w, &l1);
    hi[2 * i] = h0; hi[2 * i + 1] = h1;
    lo[2 * i] = l0; lo[2 * i + 1] = l1;
}

// ============================================================
// transpose + split: W[K,N] fp32 -> Wt_hi/lo [N,K] bf16
// ============================================================
__global__ void __launch_bounds__(256) transpose_split(const float* __restrict__ W,
                                                       __nv_bfloat16* __restrict__ Th,
                                                       __nv_bfloat16* __restrict__ Tl,
                                                       int K, int N)
{
    __shared__ float s[32][33];
    int n0 = blockIdx.x * 32, k0 = blockIdx.y * 32;
    for (int i = threadIdx.y; i < 32; i += 8)
        s[i][threadIdx.x] = W[(size_t)(k0 + i) * N + n0 + threadIdx.x];
    __syncthreads();
    for (int i = threadIdx.y; i < 32; i += 8) {
        float v = s[threadIdx.x][i];
        __nv_bfloat16 h = __float2bfloat16(v);
        size_t o = (size_t)(n0 + i) * K + k0 + threadIdx.x;
        Th[o] = h;
        Tl[o] = __float2bfloat16(v - __bfloat162float(h));
    }
}

// two source tensors (wk, wv), same shape [K, N] each, fused in one launch
__global__ void __launch_bounds__(256) transpose_split2(const float* __restrict__ Wa,
                                                        const float* __restrict__ Wb,
                                                        __nv_bfloat16* __restrict__ Tha,
                                                        __nv_bfloat16* __restrict__ Tla,
                                                        __nv_bfloat16* __restrict__ Thb,
                                                        __nv_bfloat16* __restrict__ Tlb,
                                                        int K, int N)
{
    __shared__ float s[32][33];
    const int nb = N / 32;
    const bool second = (blockIdx.x >= nb);
    const float* W = second ? Wb : Wa;
    __nv_bfloat16* Th = second ? Thb : Tha;
    __nv_bfloat16* Tl = second ? Tlb : Tla;
    int n0 = (second ? blockIdx.x - nb : blockIdx.x) * 32;
    int k0 = blockIdx.y * 32;
    for (int i = threadIdx.y; i < 32; i += 8)
        s[i][threadIdx.x] = W[(size_t)(k0 + i) * N + n0 + threadIdx.x];
    __syncthreads();
    for (int i = threadIdx.y; i < 32; i += 8) {
        float v = s[threadIdx.x][i];
        __nv_bfloat16 h = __float2bfloat16(v);
        size_t o = (size_t)(n0 + i) * K + k0 + threadIdx.x;
        Th[o] = h;
        Tl[o] = __float2bfloat16(v - __bfloat162float(h));
    }
}

// ============================================================
// RoPE sin/cos table: per (row, i<128)
// ============================================================
__global__ void __launch_bounds__(256) rope_table(const int* __restrict__ segpos)
{
    int idx = blockIdx.x * 256 + threadIdx.x;       // MM*128 total
    int row = idx >> 7, i = idx & 127;
    float pos = (float)segpos[row];
    float ts  = exp2f((float)i * (13.287712379549449f / 128.0f));
    float sv, cv;
    sincosf(pos / ts, &sv, &cv);
    g_rope[idx] = make_float2(sv, cv);
}

// ============================================================
// V transpose + split
// ============================================================
__global__ void __launch_bounds__(256) vtrans_kernel(const int* __restrict__ curind)
{
    __shared__ float s[32][33];
    int t0 = blockIdx.x * 32, d0 = blockIdx.y * 32;
    int bkv = blockIdx.z;
    int b = bkv / NKV, kv = bkv - b * NKV;
    int tx = threadIdx.x, ty = threadIdx.y;
    for (int i = ty; i < 32; i += 8)
        s[i][tx] = g_qkv[(size_t)(b * TT + t0 + i) * 4096 + 3072 + kv * HD + d0 + tx];
    __syncthreads();
    int s0 = curind[0] + t0;
    for (int i = ty; i < 32; i += 8) {
        float v = s[tx][i];
        __nv_bfloat16 h = __float2bfloat16(v);
        size_t o = ((size_t)bkv * HD + d0 + i) * SC + s0 + tx;
        g_vthi[o] = h;
        g_vtlo[o] = __float2bfloat16(v - __bfloat162float(h));
    }
}

// ============================================================
// HMMA GEMM (bf16 x3 split), 3-stage cp.async pipeline.
// C[M,N] = (Ahi+Alo)[M,K] @ (Bhi+Blo)[N,K]^T
// 128x128 CTA tile, BK=64, 8 warps (4x2), warp 32x64.  (round-8 config)
// ============================================================
#define ST_AHI 0
#define ST_ALO 16384
#define ST_BHI 32768
#define ST_BLO 49152
#define STAGE_BYTES 65536
#define GEMM_SMEM   (3 * STAGE_BYTES)       // 196608

__device__ __forceinline__ void load_stage(uint32_t sbase,
    const __nv_bfloat16* __restrict__ Ahi, const __nv_bfloat16* __restrict__ Alo,
    const __nv_bfloat16* __restrict__ Bhi, const __nv_bfloat16* __restrict__ Blo,
    int Kdim, int m0, int n0, int k0, int tid)
{
#pragma unroll
    for (int ii = 0; ii < 4; ii++) {
        int i = tid + ii * 256;
        int r = i >> 3, c = i & 7;
        uint32_t so = (uint32_t)(r * 128 + ((c ^ (r & 7)) << 4));
        size_t goA = (size_t)(m0 + r) * Kdim + k0 + c * 8;
        size_t goB = (size_t)(n0 + r) * Kdim + k0 + c * 8;
        cpasync16(sbase + ST_AHI + so, Ahi + goA);
        cpasync16(sbase + ST_ALO + so, Alo + goA);
        cpasync16(sbase + ST_BHI + so, Bhi + goB);
        cpasync16(sbase + ST_BLO + so, Blo + goB);
    }
}

__global__ void __launch_bounds__(256) gemm_bf16x3(
    const __nv_bfloat16* __restrict__ Ahi, const __nv_bfloat16* __restrict__ Alo,
    const __nv_bfloat16* __restrict__ Bhi, const __nv_bfloat16* __restrict__ Blo,
    float* __restrict__ C, int Ndim, int Kdim)
{
    extern __shared__ __align__(128) char smem[];
    const uint32_t sb = s2u(smem);
    const int tid  = threadIdx.x;
    const int wid  = tid >> 5;
    const int lane = tid & 31;
    const int wm   = wid >> 1;
    const int wn   = wid & 1;
    const int m0   = blockIdx.y * 128;
    const int n0   = blockIdx.x * 128;

    const int lrow = lane & 15;
    const int lkc  = lane >> 4;

    int arow[2], brow[4];
#pragma unroll
    for (int mt = 0; mt < 2; mt++) arow[mt] = wm * 32 + mt * 16 + lrow;
#pragma unroll
    for (int nt = 0; nt < 4; nt++) brow[nt] = wn * 64 + nt * 16 + lrow;

    float acc[2][4][2][4];
#pragma unroll
    for (int mt = 0; mt < 2; mt++)
#pragma unroll
        for (int nt = 0; nt < 4; nt++)
#pragma unroll
            for (int h = 0; h < 2; h++)
#pragma unroll
                for (int r = 0; r < 4; r++) acc[mt][nt][h][r] = 0.f;

    const int nk = Kdim >> 6;

    // 3-stage prologue
    load_stage(sb, Ahi, Alo, Bhi, Blo, Kdim, m0, n0, 0, tid);
    cp_commit();
    load_stage(sb + STAGE_BYTES, Ahi, Alo, Bhi, Blo, Kdim, m0, n0, 64, tid);
    cp_commit();

    for (int c = 0; c < nk; c++) {
        cp_wait1();          // stage c landed (one group may remain in flight)
        __syncthreads();     // all warps done with stage c-1 (same buffer as c+2)
        if (c + 2 < nk) {
            load_stage(sb + ((c + 2) % 3) * STAGE_BYTES, Ahi, Alo, Bhi, Blo,
                       Kdim, m0, n0, (c + 2) << 6, tid);
        }
        cp_commit();         // commit every iter to keep group accounting fixed

        const uint32_t st = sb + (c % 3) * STAGE_BYTES;

#pragma unroll
        for (int ks = 0; ks < 4; ks++) {
            const int chunk = ks * 2 + lkc;
            uint32_t ah[2][4], al[2][4], bh[4][4], bl[4][4];
#pragma unroll
            for (int mt = 0; mt < 2; mt++) {
                uint32_t off = (uint32_t)(arow[mt] * 128 + ((chunk ^ (arow[mt] & 7)) << 4));
                ldm4(ah[mt], st + ST_AHI + off);
                ldm4(al[mt], st + ST_ALO + off);
            }
#pragma unroll
            for (int nt = 0; nt < 4; nt++) {
                uint32_t off = (uint32_t)(brow[nt] * 128 + ((chunk ^ (brow[nt] & 7)) << 4));
                ldm4(bh[nt], st + ST_BHI + off);
                ldm4(bl[nt], st + ST_BLO + off);
            }
            // term-major: consecutive MMAs hit distinct accumulators
#pragma unroll
            for (int mt = 0; mt < 2; mt++)
#pragma unroll
                for (int nt = 0; nt < 4; nt++)
#pragma unroll
                    for (int h = 0; h < 2; h++)
                        mma16816(acc[mt][nt][h], ah[mt], bh[nt][h], bh[nt][h + 2]);
#pragma unroll
            for (int mt = 0; mt < 2; mt++)
#pragma unroll
                for (int nt = 0; nt < 4; nt++)
#pragma unroll
                    for (int h = 0; h < 2; h++)
                        mma16816(acc[mt][nt][h], ah[mt], bl[nt][h], bl[nt][h + 2]);
#pragma unroll
            for (int mt = 0; mt < 2; mt++)
#pragma unroll
                for (int nt = 0; nt < 4; nt++)
#pragma unroll
                    for (int h = 0; h < 2; h++)
                        mma16816(acc[mt][nt][h], al[mt], bh[nt][h], bh[nt][h + 2]);
        }
    }

    const int qr = lane >> 2;
    const int qc = lane & 3;
#pragma unroll
    for (int mt = 0; mt < 2; mt++) {
#pragma unroll
        for (int nt = 0; nt < 4; nt++) {
#pragma unroll
            for (int h = 0; h < 2; h++) {
                int row = m0 + wm * 32 + mt * 16 + qr;
                int col = n0 + wn * 64 + nt * 16 + h * 8 + qc * 2;
                float* d = acc[mt][nt][h];
                *(float2*)(C + (size_t)row * Ndim + col)       = make_float2(d[0], d[1]);
                *(float2*)(C + (size_t)(row + 8) * Ndim + col) = make_float2(d[2], d[3]);
            }
        }
    }
}

// ============================================================
// RMSNorm + RoPE (table) -> bf16 hi/lo operand caches
// ============================================================
__global__ void __launch_bounds__(256) normrope_kernel(const int* __restrict__ segpos,
                                                       const int* __restrict__ curind,
                                                       const float* __restrict__ qns,
                                                       const float* __restrict__ kns)
{
    const int row  = blockIdx.x;
    const int slot = blockIdx.y;
    const int d    = threadIdx.x;
    const int b    = row / TT;
    const int t    = row - b * TT;

    const float* src;
    const float* sc;
    if (slot < NH) {
        src = g_qkv + (size_t)row * 4096 + slot * HD;
        sc  = qns;
    } else {
        src = g_qkv + (size_t)row * 4096 + 2048 + (slot - NH) * HD;
        sc  = kns;
    }

    float v  = src[d];
    float ss = v * v;
#pragma unroll
    for (int o = 16; o > 0; o >>= 1) ss += __shfl_xor_sync(0xffffffffu, ss, o);

    __shared__ float wsum[8];
    __shared__ float s_n[HD];
    __shared__ float s_r;
    if ((d & 31) == 0) wsum[d >> 5] = ss;
    __syncthreads();
    if (d == 0) {
        float tot = 0.f;
#pragma unroll
        for (int w = 0; w < 8; w++) tot += wsum[w];
        s_r = rsqrtf(tot * (1.0f / HD) + 1e-6f);
    }
    __syncthreads();

    float n = v * s_r * (1.0f + sc[d]);
    s_n[d] = n;
    __syncthreads();

    float2 sc2 = g_rope[(size_t)row * 128 + (d & 127)];
    float outv = (d < 128) ? (n * sc2.y - s_n[d + 128] * sc2.x)
                           : (n * sc2.y + s_n[d - 128] * sc2.x);

    if (slot < NH) {
        outv *= 0.0625f;   // fold HD^-1/2
        size_t o = ((size_t)(b * NH + slot) * TT + t) * HD + d;
        __nv_bfloat16 h = __float2bfloat16(outv);
        g_qhi[o] = h;
        g_qlo[o] = __float2bfloat16(outv - __bfloat162float(h));
    } else {
        int kv = slot - NH;
        int ct = curind[0] + t;
        size_t o = ((size_t)(b * NKV + kv) * SC + ct) * HD + d;
        __nv_bfloat16 h = __float2bfloat16(outv);
        g_khi[o] = h;
        g_klo[o] = __float2bfloat16(outv - __bfloat162float(h));
    }
}

// ============================================================
// HMMA windowed attention, double-buffered K/V chunk pipeline.
// Block: 64 queries x one (b,h); 256 threads = 8 warps.
// ============================================================
#define ATQ 64
#define ACK 32
// smem byte offsets
#define SQH 0                          // Q hi: 4 subtiles x 64 x 128B = 32768
#define SQL 32768
#define SKB0 65536                     // K stage: hi 16384 + lo 16384; x2 stages
#define SK_STRIDE 32768
#define SVB0 131072                    // V stage: hi 20480 + lo 20480; x2 stages
#define SV_STRIDE 40960
#define SPH 212992                     // P hi: 64 x 80B
#define SPL 218112
#define SPS 223232                     // psum[2][64] fp32
#define ATTN_SMEM 223744

__device__ __forceinline__ float capexp(float a, int pos, int s) {
    float e = __expf(a * 0.04f);                       // e^{2a/50}
    float t = 50.0f * __fdividef(e - 1.0f, e + 1.0f);  // 50*tanh(a/50)
    bool valid = (s <= pos) && (pos - s < WIN);
    return valid ? __expf(t) : 0.0f;
}

__device__ __forceinline__ void attn_load_chunk(char* sm, uint32_t sb, int buf,
                                                int s0, int bkv, int tid)
{
    const uint32_t kb = sb + SKB0 + buf * SK_STRIDE;
    const uint32_t ko = SKB0 + buf * SK_STRIDE;
    for (int i = tid; i < 32 * 32; i += 256) {
        int r = i >> 5, c = i & 31;
        int s = s0 + r;
        int sub = c >> 3, cc = c & 7;
        uint32_t so = (uint32_t)(sub * 4096 + r * 128 + ((cc ^ (r & 7)) << 4));
        if (s < SC) {
            size_t go = ((size_t)bkv * SC + s) * HD + c * 8;
            cpasync16(kb + so, g_khi + go);
            cpasync16(kb + 16384 + so, g_klo + go);
        } else {
            *(uint4*)(sm + ko + so)         = make_uint4(0, 0, 0, 0);
            *(uint4*)(sm + ko + 16384 + so) = make_uint4(0, 0, 0, 0);
        }
    }
    const uint32_t vb = sb + SVB0 + buf * SV_STRIDE;
    const uint32_t vo = SVB0 + buf * SV_STRIDE;
    for (int i = tid; i < 256 * 4; i += 256) {
        int dd = i >> 2, c = i & 3;
        uint32_t so = (uint32_t)(dd * 80 + c * 16);
        if (s0 + c * 8 + 7 < SC) {
            size_t go = ((size_t)bkv * HD + dd) * SC + s0 + c * 8;
            cpasync16(vb + so, g_vthi + go);
            cpasync16(vb + 20480 + so, g_vtlo + go);
        } else {
            *(uint4*)(sm + vo + so)         = make_uint4(0, 0, 0, 0);
            *(uint4*)(sm + vo + 20480 + so) = make_uint4(0, 0, 0, 0);
        }
    }
}

__global__ void __launch_bounds__(256) attn_mma(const int* __restrict__ segpos)
{
    extern __shared__ __align__(128) char sm[];
    const uint32_t sb = s2u(sm);
    const int tid  = threadIdx.x;
    const int wid  = tid >> 5;
    const int lane = tid & 31;
    const int t0   = blockIdx.x * ATQ;
    const int head = blockIdx.y;
    const int b    = blockIdx.z;
    const int kv   = head / GRP;
    const int bkv  = b * NKV + kv;
    const int wm   = wid >> 1;
    const int wh   = wid & 1;
    const int lrow = lane & 15;
    const int lkc  = lane >> 4;
    const int qr   = lane >> 2;
    const int qc   = lane & 3;

    float* psum = (float*)(sm + SPS);

    // window bounds (direct global reads; same addr across warp -> broadcast)
    int minp, maxp;
    {
        const int* sp = segpos + b * TT + t0;
        minp = sp[0]; maxp = sp[0];
#pragma unroll 8
        for (int i = 1; i < ATQ; i++) {
            int p = sp[i];
            minp = min(minp, p);
            maxp = max(maxp, p);
        }
    }
    const int smin = max(0, minp - (WIN - 1)) & ~31;
    const int smax = min(SC - 1, maxp);
    const int nchunks = ((smax - smin) >> 5) + 1;

    const int myp0 = segpos[b * TT + t0 + wm * 16 + qr];
    const int myp1 = segpos[b * TT + t0 + wm * 16 + qr + 8];

    if (tid < 2 * ATQ) psum[tid] = 0.f;

    // prologue: Q tile + chunk 0  (one commit group)
    {
        const __nv_bfloat16* gh = g_qhi + ((size_t)(b * NH + head) * TT + t0) * HD;
        const __nv_bfloat16* gl = g_qlo + ((size_t)(b * NH + head) * TT + t0) * HD;
        for (int i = tid; i < ATQ * 32; i += 256) {
            int r = i >> 5, c = i & 31;
            int sub = c >> 3, cc = c & 7;
            uint32_t so = (uint32_t)(sub * 8192 + r * 128 + ((cc ^ (r & 7)) << 4));
            cpasync16(sb + SQH + so, gh + (size_t)r * HD + c * 8);
            cpasync16(sb + SQL + so, gl + (size_t)r * HD + c * 8);
        }
        attn_load_chunk(sm, sb, 0, smin, bkv, tid);
    }
    cp_commit();

    float oacc[16][4];
#pragma unroll
    for (int i = 0; i < 16; i++)
#pragma unroll
        for (int r = 0; r < 4; r++) oacc[i][r] = 0.f;

    for (int ci = 0; ci < nchunks; ci++) {
        const int s0 = smin + ci * ACK;
        __syncthreads();                       // prev PV done (protects buf ci+1 overwrite)
        if (ci + 1 < nchunks)
            attn_load_chunk(sm, sb, (ci + 1) & 1, s0 + ACK, bkv, tid);
        cp_commit();
        cp_wait1();                            // chunk ci (and Q on ci=0) ready
        __syncthreads();

        const uint32_t kb = sb + SKB0 + (ci & 1) * SK_STRIDE;
        const uint32_t vb = sb + SVB0 + (ci & 1) * SV_STRIDE;

        // ---- QK^T : m16 x n16 per warp, k = 256 ----
        float sacc[2][4];
#pragma unroll
        for (int hh = 0; hh < 2; hh++)
#pragma unroll
            for (int r = 0; r < 4; r++) sacc[hh][r] = 0.f;

        const int arow = wm * 16 + lrow;
        const int brow = wh * 16 + lrow;
#pragma unroll
        for (int ks = 0; ks < 16; ks++) {
            int sub = ks >> 2, cc = (ks & 3) * 2 + lkc;
            uint32_t ao = (uint32_t)(sub * 8192 + arow * 128 + ((cc ^ (arow & 7)) << 4));
            uint32_t bo = (uint32_t)(sub * 4096 + brow * 128 + ((cc ^ (brow & 7)) << 4));
            uint32_t ah[4], al[4], bh[4], bl[4];
            ldm4(ah, sb + SQH + ao);
            ldm4(al, sb + SQL + ao);
            ldm4(bh, kb + bo);
            ldm4(bl, kb + 16384 + bo);
#pragma unroll
            for (int hh = 0; hh < 2; hh++) mma16816(sacc[hh], ah, bh[hh], bh[hh + 2]);
#pragma unroll
            for (int hh = 0; hh < 2; hh++) mma16816(sacc[hh], ah, bl[hh], bl[hh + 2]);
#pragma unroll
            for (int hh = 0; hh < 2; hh++) mma16816(sacc[hh], al, bh[hh], bh[hh + 2]);
        }

        // ---- softcap + mask + exp; write P hi/lo; partial row sums ----
        float rs0 = 0.f, rs1 = 0.f;
#pragma unroll
        for (int hh = 0; hh < 2; hh++) {
            int colL = wh * 16 + hh * 8 + 2 * qc;
            int colG = s0 + colL;
            float p00 = capexp(sacc[hh][0], myp0, colG);
            float p01 = capexp(sacc[hh][1], myp0, colG + 1);
            float p10 = capexp(sacc[hh][2], myp1, colG);
            float p11 = capexp(sacc[hh][3], myp1, colG + 1);
            rs0 += p00 + p01;
            rs1 += p10 + p11;
            __nv_bfloat162 lo0, lo1;
            __nv_bfloat162 hi0 = split_pack_hi(p00, p01, &lo0);
            __nv_bfloat162 hi1 = split_pack_hi(p10, p11, &lo1);
            int r0 = wm * 16 + qr;
            uint32_t o0 = (uint32_t)(r0 * 80 + colL * 2);
            uint32_t o1 = o0 + 8 * 80;
            *(__nv_bfloat162*)(sm + SPH + o0) = hi0;
            *(__nv_bfloat162*)(sm + SPL + o0) = lo0;
            *(__nv_bfloat162*)(sm + SPH + o1) = hi1;
            *(__nv_bfloat162*)(sm + SPL + o1) = lo1;
        }
        rs0 += __shfl_xor_sync(0xffffffffu, rs0, 1);
        rs0 += __shfl_xor_sync(0xffffffffu, rs0, 2);
        rs1 += __shfl_xor_sync(0xffffffffu, rs1, 1);
        rs1 += __shfl_xor_sync(0xffffffffu, rs1, 2);
        if (qc == 0) {
            psum[wh * 64 + wm * 16 + qr]     += rs0;
            psum[wh * 64 + wm * 16 + qr + 8] += rs1;
        }
        __syncthreads();

        // ---- P @ V : m16 x d128 per warp, k = 32 ----
        const int prow = wm * 16 + lrow;
#pragma unroll
        for (int ks2 = 0; ks2 < 2; ks2++) {
            uint32_t po = (uint32_t)(prow * 80 + ((ks2 * 2 + lkc) << 4));
            uint32_t ph[4], pl[4];
            ldm4(ph, sb + SPH + po);
            ldm4(pl, sb + SPL + po);
            uint32_t vh4[8][4], vl4[8][4];
#pragma unroll
            for (int nt = 0; nt < 8; nt++) {
                int vrow = wh * 128 + nt * 16 + lrow;
                uint32_t vo = (uint32_t)(vrow * 80 + ((ks2 * 2 + lkc) << 4));
                ldm4(vh4[nt], vb + vo);
                ldm4(vl4[nt], vb + 20480 + vo);
            }
#pragma unroll
            for (int nt = 0; nt < 8; nt++)
#pragma unroll
                for (int hh = 0; hh < 2; hh++)
                    mma16816(oacc[nt * 2 + hh], ph, vh4[nt][hh], vh4[nt][hh + 2]);
#pragma unroll
            for (int nt = 0; nt < 8; nt++)
#pragma unroll
                for (int hh = 0; hh < 2; hh++)
                    mma16816(oacc[nt * 2 + hh], ph, vl4[nt][hh], vl4[nt][hh + 2]);
#pragma unroll
            for (int nt = 0; nt < 8; nt++)
#pragma unroll
                for (int hh = 0; hh < 2; hh++)
                    mma16816(oacc[nt * 2 + hh], pl, vh4[nt][hh], vh4[nt][hh + 2]);
        }
    }

    // ---- epilogue: divide by row sums, write bf16 hi/lo for O-proj ----
    const int r0 = wm * 16 + qr;
    const float inv0 = __fdividef(1.0f, psum[r0] + psum[64 + r0]);
    const float inv1 = __fdividef(1.0f, psum[r0 + 8] + psum[64 + r0 + 8]);
    const size_t tok0 = (size_t)(b * TT + t0 + r0);
#pragma unroll
    for (int nt = 0; nt < 8; nt++) {
#pragma unroll
        for (int hh = 0; hh < 2; hh++) {
            int col = head * HD + wh * 128 + nt * 16 + hh * 8 + 2 * qc;
            float* d = oacc[nt * 2 + hh];
            __nv_bfloat162 lo0, lo1;
            __nv_bfloat162 hi0 = split_pack_hi(d[0] * inv0, d[1] * inv0, &lo0);
            __nv_bfloat162 hi1 = split_pack_hi(d[2] * inv1, d[3] * inv1, &lo1);
            *(__nv_bfloat162*)(g_ahi + tok0 * 2048 + col)       = hi0;
            *(__nv_bfloat162*)(g_alo + tok0 * 2048 + col)       = lo0;
            *(__nv_bfloat162*)(g_ahi + (tok0 + 8) * 2048 + col) = hi1;
            *(__nv_bfloat162*)(g_alo + (tok0 + 8) * 2048 + col) = lo1;
        }
    }
}

// ============================================================
// Launch  (order chosen so ncu -s 5 -c 1 profiles the QKV GEMM)
//   0: convert_split   1: rope_table   2: transpose(wq)
//   3: transpose2(wk,wv)   4: transpose(wo)   5: QKV GEMM  <- profiled
//   6: normrope   7: vtrans   8: attn   9: O GEMM
// ============================================================
extern "C" void kernel_launch(void* const* d_in, const int* in_sizes, int n_in,
                              void* d_out, int out_size)
{
    const float* x      = (const float*)d_in[0];
    const int*   segpos = (const int*)  d_in[1];
    const int*   curind = (const int*)  d_in[2];
    const float* wq     = (const float*)d_in[3];
    const float* wk     = (const float*)d_in[4];
    const float* wv     = (const float*)d_in[5];
    const float* wo     = (const float*)d_in[6];
    const float* qns    = (const float*)d_in[7];
    const float* kns    = (const float*)d_in[8];
    float* out = (float*)d_out;

    float* gqkv;
    __nv_bfloat16 *xhi, *xlo, *ahi, *alo, *wthi, *wtlo;
    cudaGetSymbolAddress((void**)&gqkv, g_qkv);
    cudaGetSymbolAddress((void**)&xhi,  g_xhi);
    cudaGetSymbolAddress((void**)&xlo,  g_xlo);
    cudaGetSymbolAddress((void**)&ahi,  g_ahi);
    cudaGetSymbolAddress((void**)&alo,  g_alo);
    cudaGetSymbolAddress((void**)&wthi, g_wthi);
    cudaGetSymbolAddress((void**)&wtlo, g_wtlo);

    cudaFuncSetAttribute(gemm_bf16x3, cudaFuncAttributeMaxDynamicSharedMemorySize, GEMM_SMEM);
    cudaFuncSetAttribute(attn_mma, cudaFuncAttributeMaxDynamicSharedMemorySize, ATTN_SMEM);

    // 0) split x into bf16 hi/lo
    {
        int n4 = (MM * DD) / 4;
        convert_split<<<n4 / 256, 256>>>((const float4*)x,
                                         (__nv_bfloat162*)xhi, (__nv_bfloat162*)xlo, n4);
    }
    // 1) rope table
    rope_table<<<(MM * 128) / 256, 256>>>(segpos);

    // 2-4) transpose + split weights
    transpose_split<<<dim3(DD / 32, DD / 32), dim3(32, 8)>>>(wq, wthi + WQ_OFF, wtlo + WQ_OFF, DD, DD);
    transpose_split2<<<dim3(2 * (NKV * HD) / 32, DD / 32), dim3(32, 8)>>>(
        wk, wv, wthi + WK_OFF, wtlo + WK_OFF, wthi + WV_OFF, wtlo + WV_OFF, DD, NKV * HD);
    transpose_split<<<dim3(DD / 32, DD / 32), dim3(32, 8)>>>(wo, wthi + WO_OFF, wtlo + WO_OFF, NH * HD, DD);

    // 5) fused QKV projection  <- ncu profiles this launch
    gemm_bf16x3<<<dim3(4096 / 128, MM / 128), 256, GEMM_SMEM>>>(
        xhi, xlo, wthi, wtlo, gqkv, 4096, DD);

    // 6-7) norm + rope -> bf16 hi/lo q + k-cache ; v transpose -> vt cache
    normrope_kernel<<<dim3(MM, NH + NKV), 256>>>(segpos, curind, qns, kns);
    vtrans_kernel<<<dim3(TT / 32, HD / 32, BB * NKV), dim3(32, 8)>>>(curind);

    // 8) HMMA attention -> g_ahi/g_alo
    attn_mma<<<dim3(TT / ATQ, NH, BB), 256, ATTN_SMEM>>>(segpos);

    // 9) output projection -> d_out
    gemm_bf16x3<<<dim3(DD / 128, MM / 128), 256, GEMM_SMEM>>>(
        ahi, alo, wthi + WO_OFF, wtlo + WO_OFF, out, DD, NH * HD);
}

// round 13
// speedup vs baseline: 1.1261x; 1.0820x over previous
#include <cuda_runtime.h>
#include <cuda_bf16.h>
#include <cuda_fp16.h>
#include <math.h>
#include <cstdint>

// ---- problem constants ----
#define BB   2
#define TT   2048
#define DD   2048
#define NH   8
#define NKV  4
#define HD   256
#define SC   2048
#define WIN  512
#define GRP  (NH / NKV)   // 2
#define MM   (BB * TT)    // 4096

// ---- device scratch ----
__device__ float g_qkv[(size_t)MM * 4096];              // fused projection output (fp32)
__device__ float2 g_rope[(size_t)MM * 128];             // per-(row, i) sin/cos

__device__ __nv_bfloat16 g_xhi[(size_t)MM * DD], g_xlo[(size_t)MM * DD];
// attention output, fp16 hi/lo (A-operand of O projection)
__device__ __half g_ahi[(size_t)MM * NH * HD], g_alo[(size_t)MM * NH * HD];

// attention operand caches, bf16 hi/lo
__device__ __nv_bfloat16 g_qhi[(size_t)BB * NH * TT * HD], g_qlo[(size_t)BB * NH * TT * HD];
__device__ __nv_bfloat16 g_khi[(size_t)BB * NKV * SC * HD], g_klo[(size_t)BB * NKV * SC * HD];
__device__ __nv_bfloat16 g_vthi[(size_t)BB * NKV * HD * SC], g_vtlo[(size_t)BB * NKV * HD * SC];

#define WQ_OFF 0
#define WK_OFF ((size_t)DD * DD)
#define WV_OFF (WK_OFF + (size_t)DD * NKV * HD)
#define W_TOT  (WV_OFF + (size_t)DD * NKV * HD)
__device__ __nv_bfloat16 g_wthi[W_TOT], g_wtlo[W_TOT];  // wq/wk/wv transposed [N,K], hi/lo
__device__ __half g_wohi[(size_t)DD * DD];              // wo transposed [N,K], fp16 hi only

// ============================================================
// helpers
// ============================================================
__device__ __forceinline__ uint32_t s2u(const void* p) {
    uint32_t a;
    asm("{ .reg .u64 t; cvta.to.shared.u64 t, %1; cvt.u32.u64 %0, t; }" : "=r"(a) : "l"(p));
    return a;
}
__device__ __forceinline__ void cpasync16(uint32_t saddr, const void* gaddr) {
    asm volatile("cp.async.cg.shared.global [%0], [%1], 16;" :: "r"(saddr), "l"(gaddr));
}
__device__ __forceinline__ void cp_commit() {
    asm volatile("cp.async.commit_group;" ::: "memory");
}
__device__ __forceinline__ void cp_wait1() {
    asm volatile("cp.async.wait_group 1;" ::: "memory");
}
__device__ __forceinline__ void cp_wait0() {
    asm volatile("cp.async.wait_group 0;" ::: "memory");
}
__device__ __forceinline__ void ldm4(uint32_t* d, uint32_t addr) {
    asm volatile("ldmatrix.sync.aligned.m8n8.x4.shared.b16 {%0,%1,%2,%3}, [%4];"
                 : "=r"(d[0]), "=r"(d[1]), "=r"(d[2]), "=r"(d[3]) : "r"(addr));
}
__device__ __forceinline__ void mma16816(float* c, const uint32_t* a, uint32_t b0, uint32_t b1) {
    asm volatile("mma.sync.aligned.m16n8k16.row.col.f32.bf16.bf16.f32 "
                 "{%0,%1,%2,%3}, {%4,%5,%6,%7}, {%8,%9}, {%0,%1,%2,%3};"
                 : "+f"(c[0]), "+f"(c[1]), "+f"(c[2]), "+f"(c[3])
                 : "r"(a[0]), "r"(a[1]), "r"(a[2]), "r"(a[3]), "r"(b0), "r"(b1));
}
__device__ __forceinline__ void mma16816h(float* c, const uint32_t* a, uint32_t b0, uint32_t b1) {
    asm volatile("mma.sync.aligned.m16n8k16.row.col.f32.f16.f16.f32 "
                 "{%0,%1,%2,%3}, {%4,%5,%6,%7}, {%8,%9}, {%0,%1,%2,%3};"
                 : "+f"(c[0]), "+f"(c[1]), "+f"(c[2]), "+f"(c[3])
                 : "r"(a[0]), "r"(a[1]), "r"(a[2]), "r"(a[3]), "r"(b0), "r"(b1));
}
__device__ __forceinline__ __nv_bfloat162 split_pack_hi(float a, float b,
                                                        __nv_bfloat162* lo) {
    __nv_bfloat16 ha = __float2bfloat16(a), hb = __float2bfloat16(b);
    *lo = __halves2bfloat162(__float2bfloat16(a - __bfloat162float(ha)),
                             __float2bfloat16(b - __bfloat162float(hb)));
    return __halves2bfloat162(ha, hb);
}
__device__ __forceinline__ __half2 split_pack_hi_h(float a, float b, __half2* lo) {
    __half ha = __float2half_rn(a), hb = __float2half_rn(b);
    *lo = __halves2half2(__float2half_rn(a - __half2float(ha)),
                         __float2half_rn(b - __half2float(hb)));
    return __halves2half2(ha, hb);
}

// ============================================================
// convert: fp32 -> (hi, lo) bf16 pair, vectorized x4
// ============================================================
__global__ void __launch_bounds__(256) convert_split(const float4* __restrict__ src,
                                                     __nv_bfloat162* __restrict__ hi,
                                                     __nv_bfloat162* __restrict__ lo,
                                                     int n4)
{
    int i = blockIdx.x * 256 + threadIdx.x;
    if (i >= n4) return;
    float4 v = src[i];
    __nv_bfloat162 l0, l1;
    __nv_bfloat162 h0 = split_pack_hi(v.x, v.y, &l0);
    __nv_bfloat162 h1 = split_pack_hi(v.z, v.w, &l1);
    hi[2 * i] = h0; hi[2 * i + 1] = h1;
    lo[2 * i] = l0; lo[2 * i + 1] = l1;
}

// ============================================================
// transpose + split: W[K,N] fp32 -> Wt_hi/lo [N,K] bf16
// ============================================================
__global__ void __launch_bounds__(256) transpose_split(const float* __restrict__ W,
                                                       __nv_bfloat16* __restrict__ Th,
                                                       __nv_bfloat16* __restrict__ Tl,
                                                       int K, int N)
{
    __shared__ float s[32][33];
    int n0 = blockIdx.x * 32, k0 = blockIdx.y * 32;
    for (int i = threadIdx.y; i < 32; i += 8)
        s[i][threadIdx.x] = W[(size_t)(k0 + i) * N + n0 + threadIdx.x];
    __syncthreads();
    for (int i = threadIdx.y; i < 32; i += 8) {
        float v = s[threadIdx.x][i];
        __nv_bfloat16 h = __float2bfloat16(v);
        size_t o = (size_t)(n0 + i) * K + k0 + threadIdx.x;
        Th[o] = h;
        Tl[o] = __float2bfloat16(v - __bfloat162float(h));
    }
}

// two source tensors (wk, wv), same shape [K, N] each, fused in one launch
__global__ void __launch_bounds__(256) transpose_split2(const float* __restrict__ Wa,
                                                        const float* __restrict__ Wb,
                                                        __nv_bfloat16* __restrict__ Tha,
                                                        __nv_bfloat16* __restrict__ Tla,
                                                        __nv_bfloat16* __restrict__ Thb,
                                                        __nv_bfloat16* __restrict__ Tlb,
                                                        int K, int N)
{
    __shared__ float s[32][33];
    const int nb = N / 32;
    const bool second = (blockIdx.x >= nb);
    const float* W = second ? Wb : Wa;
    __nv_bfloat16* Th = second ? Thb : Tha;
    __nv_bfloat16* Tl = second ? Tlb : Tla;
    int n0 = (second ? blockIdx.x - nb : blockIdx.x) * 32;
    int k0 = blockIdx.y * 32;
    for (int i = threadIdx.y; i < 32; i += 8)
        s[i][threadIdx.x] = W[(size_t)(k0 + i) * N + n0 + threadIdx.x];
    __syncthreads();
    for (int i = threadIdx.y; i < 32; i += 8) {
        float v = s[threadIdx.x][i];
        __nv_bfloat16 h = __float2bfloat16(v);
        size_t o = (size_t)(n0 + i) * K + k0 + threadIdx.x;
        Th[o] = h;
        Tl[o] = __float2bfloat16(v - __bfloat162float(h));
    }
}

// transpose to fp16 hi only (wo)
__global__ void __launch_bounds__(256) transpose_h(const float* __restrict__ W,
                                                   __half* __restrict__ Th,
                                                   int K, int N)
{
    __shared__ float s[32][33];
    int n0 = blockIdx.x * 32, k0 = blockIdx.y * 32;
    for (int i = threadIdx.y; i < 32; i += 8)
        s[i][threadIdx.x] = W[(size_t)(k0 + i) * N + n0 + threadIdx.x];
    __syncthreads();
    for (int i = threadIdx.y; i < 32; i += 8) {
        size_t o = (size_t)(n0 + i) * K + k0 + threadIdx.x;
        Th[o] = __float2half_rn(s[threadIdx.x][i]);
    }
}

// ============================================================
// RoPE sin/cos table: per (row, i<128)
// ============================================================
__global__ void __launch_bounds__(256) rope_table(const int* __restrict__ segpos)
{
    int idx = blockIdx.x * 256 + threadIdx.x;       // MM*128 total
    int row = idx >> 7, i = idx & 127;
    float pos = (float)segpos[row];
    float ts  = exp2f((float)i * (13.287712379549449f / 128.0f));
    float sv, cv;
    sincosf(pos / ts, &sv, &cv);
    g_rope[idx] = make_float2(sv, cv);
}

// ============================================================
// V transpose + split
// ============================================================
__global__ void __launch_bounds__(256) vtrans_kernel(const int* __restrict__ curind)
{
    __shared__ float s[32][33];
    int t0 = blockIdx.x * 32, d0 = blockIdx.y * 32;
    int bkv = blockIdx.z;
    int b = bkv / NKV, kv = bkv - b * NKV;
    int tx = threadIdx.x, ty = threadIdx.y;
    for (int i = ty; i < 32; i += 8)
        s[i][tx] = g_qkv[(size_t)(b * TT + t0 + i) * 4096 + 3072 + kv * HD + d0 + tx];
    __syncthreads();
    int s0 = curind[0] + t0;
    for (int i = ty; i < 32; i += 8) {
        float v = s[tx][i];
        __nv_bfloat16 h = __float2bfloat16(v);
        size_t o = ((size_t)bkv * HD + d0 + i) * SC + s0 + tx;
        g_vthi[o] = h;
        g_vtlo[o] = __float2bfloat16(v - __bfloat162float(h));
    }
}

// ============================================================
// HMMA GEMM (bf16 x3 split), 3-stage cp.async pipeline.
// C[M,N] = (Ahi+Alo)[M,K] @ (Bhi+Blo)[N,K]^T
// 128x128 CTA tile, BK=64, 8 warps (4x2), warp 32x64.  (round-8 config)
// ============================================================
#define ST_AHI 0
#define ST_ALO 16384
#define ST_BHI 32768
#define ST_BLO 49152
#define STAGE_BYTES 65536
#define GEMM_SMEM   (3 * STAGE_BYTES)       // 196608

__device__ __forceinline__ void load_stage(uint32_t sbase,
    const __nv_bfloat16* __restrict__ Ahi, const __nv_bfloat16* __restrict__ Alo,
    const __nv_bfloat16* __restrict__ Bhi, const __nv_bfloat16* __restrict__ Blo,
    int Kdim, int m0, int n0, int k0, int tid)
{
#pragma unroll
    for (int ii = 0; ii < 4; ii++) {
        int i = tid + ii * 256;
        int r = i >> 3, c = i & 7;
        uint32_t so = (uint32_t)(r * 128 + ((c ^ (r & 7)) << 4));
        size_t goA = (size_t)(m0 + r) * Kdim + k0 + c * 8;
        size_t goB = (size_t)(n0 + r) * Kdim + k0 + c * 8;
        cpasync16(sbase + ST_AHI + so, Ahi + goA);
        cpasync16(sbase + ST_ALO + so, Alo + goA);
        cpasync16(sbase + ST_BHI + so, Bhi + goB);
        cpasync16(sbase + ST_BLO + so, Blo + goB);
    }
}

__global__ void __launch_bounds__(256) gemm_bf16x3(
    const __nv_bfloat16* __restrict__ Ahi, const __nv_bfloat16* __restrict__ Alo,
    const __nv_bfloat16* __restrict__ Bhi, const __nv_bfloat16* __restrict__ Blo,
    float* __restrict__ C, int Ndim, int Kdim)
{
    extern __shared__ __align__(128) char smem[];
    const uint32_t sb = s2u(smem);
    const int tid  = threadIdx.x;
    const int wid  = tid >> 5;
    const int lane = tid & 31;
    const int wm   = wid >> 1;
    const int wn   = wid & 1;
    const int m0   = blockIdx.y * 128;
    const int n0   = blockIdx.x * 128;

    const int lrow = lane & 15;
    const int lkc  = lane >> 4;

    int arow[2], brow[4];
#pragma unroll
    for (int mt = 0; mt < 2; mt++) arow[mt] = wm * 32 + mt * 16 + lrow;
#pragma unroll
    for (int nt = 0; nt < 4; nt++) brow[nt] = wn * 64 + nt * 16 + lrow;

    float acc[2][4][2][4];
#pragma unroll
    for (int mt = 0; mt < 2; mt++)
#pragma unroll
        for (int nt = 0; nt < 4; nt++)
#pragma unroll
            for (int h = 0; h < 2; h++)
#pragma unroll
                for (int r = 0; r < 4; r++) acc[mt][nt][h][r] = 0.f;

    const int nk = Kdim >> 6;

    // 3-stage prologue
    load_stage(sb, Ahi, Alo, Bhi, Blo, Kdim, m0, n0, 0, tid);
    cp_commit();
    load_stage(sb + STAGE_BYTES, Ahi, Alo, Bhi, Blo, Kdim, m0, n0, 64, tid);
    cp_commit();

    for (int c = 0; c < nk; c++) {
        cp_wait1();
        __syncthreads();
        if (c + 2 < nk) {
            load_stage(sb + ((c + 2) % 3) * STAGE_BYTES, Ahi, Alo, Bhi, Blo,
                       Kdim, m0, n0, (c + 2) << 6, tid);
        }
        cp_commit();

        const uint32_t st = sb + (c % 3) * STAGE_BYTES;

#pragma unroll
        for (int ks = 0; ks < 4; ks++) {
            const int chunk = ks * 2 + lkc;
            uint32_t ah[2][4], al[2][4], bh[4][4], bl[4][4];
#pragma unroll
            for (int mt = 0; mt < 2; mt++) {
                uint32_t off = (uint32_t)(arow[mt] * 128 + ((chunk ^ (arow[mt] & 7)) << 4));
                ldm4(ah[mt], st + ST_AHI + off);
                ldm4(al[mt], st + ST_ALO + off);
            }
#pragma unroll
            for (int nt = 0; nt < 4; nt++) {
                uint32_t off = (uint32_t)(brow[nt] * 128 + ((chunk ^ (brow[nt] & 7)) << 4));
                ldm4(bh[nt], st + ST_BHI + off);
                ldm4(bl[nt], st + ST_BLO + off);
            }
#pragma unroll
            for (int mt = 0; mt < 2; mt++)
#pragma unroll
                for (int nt = 0; nt < 4; nt++)
#pragma unroll
                    for (int h = 0; h < 2; h++)
                        mma16816(acc[mt][nt][h], ah[mt], bh[nt][h], bh[nt][h + 2]);
#pragma unroll
            for (int mt = 0; mt < 2; mt++)
#pragma unroll
                for (int nt = 0; nt < 4; nt++)
#pragma unroll
                    for (int h = 0; h < 2; h++)
                        mma16816(acc[mt][nt][h], ah[mt], bl[nt][h], bl[nt][h + 2]);
#pragma unroll
            for (int mt = 0; mt < 2; mt++)
#pragma unroll
                for (int nt = 0; nt < 4; nt++)
#pragma unroll
                    for (int h = 0; h < 2; h++)
                        mma16816(acc[mt][nt][h], al[mt], bh[nt][h], bh[nt][h + 2]);
        }
    }

    const int qr = lane >> 2;
    const int qc = lane & 3;
#pragma unroll
    for (int mt = 0; mt < 2; mt++) {
#pragma unroll
        for (int nt = 0; nt < 4; nt++) {
#pragma unroll
            for (int h = 0; h < 2; h++) {
                int row = m0 + wm * 32 + mt * 16 + qr;
                int col = n0 + wn * 64 + nt * 16 + h * 8 + qc * 2;
                float* d = acc[mt][nt][h];
                *(float2*)(C + (size_t)row * Ndim + col)       = make_float2(d[0], d[1]);
                *(float2*)(C + (size_t)(row + 8) * Ndim + col) = make_float2(d[2], d[3]);
            }
        }
    }
}

// ============================================================
// HMMA GEMM fp16 x2-product: C = (Ahi+Alo)[M,K] @ Bhi[N,K]^T
// Same pipeline/tile as gemm_bf16x3; B has hi only. Stage = 48KB.
// ============================================================
#define H_AHI 0
#define H_ALO 16384
#define H_BHI 32768
#define H_STAGE 49152
#define GEMMH_SMEM (3 * H_STAGE)            // 147456

__device__ __forceinline__ void load_stage_h(uint32_t sbase,
    const __half* __restrict__ Ahi, const __half* __restrict__ Alo,
    const __half* __restrict__ Bhi,
    int Kdim, int m0, int n0, int k0, int tid)
{
#pragma unroll
    for (int ii = 0; ii < 4; ii++) {
        int i = tid + ii * 256;
        int r = i >> 3, c = i & 7;
        uint32_t so = (uint32_t)(r * 128 + ((c ^ (r & 7)) << 4));
        size_t goA = (size_t)(m0 + r) * Kdim + k0 + c * 8;
        size_t goB = (size_t)(n0 + r) * Kdim + k0 + c * 8;
        cpasync16(sbase + H_AHI + so, Ahi + goA);
        cpasync16(sbase + H_ALO + so, Alo + goA);
        cpasync16(sbase + H_BHI + so, Bhi + goB);
    }
}

__global__ void __launch_bounds__(256) gemm_fp16x2(
    const __half* __restrict__ Ahi, const __half* __restrict__ Alo,
    const __half* __restrict__ Bhi,
    float* __restrict__ C, int Ndim, int Kdim)
{
    extern __shared__ __align__(128) char smem[];
    const uint32_t sb = s2u(smem);
    const int tid  = threadIdx.x;
    const int wid  = tid >> 5;
    const int lane = tid & 31;
    const int wm   = wid >> 1;
    const int wn   = wid & 1;
    const int m0   = blockIdx.y * 128;
    const int n0   = blockIdx.x * 128;

    const int lrow = lane & 15;
    const int lkc  = lane >> 4;

    int arow[2], brow[4];
#pragma unroll
    for (int mt = 0; mt < 2; mt++) arow[mt] = wm * 32 + mt * 16 + lrow;
#pragma unroll
    for (int nt = 0; nt < 4; nt++) brow[nt] = wn * 64 + nt * 16 + lrow;

    float acc[2][4][2][4];
#pragma unroll
    for (int mt = 0; mt < 2; mt++)
#pragma unroll
        for (int nt = 0; nt < 4; nt++)
#pragma unroll
            for (int h = 0; h < 2; h++)
#pragma unroll
                for (int r = 0; r < 4; r++) acc[mt][nt][h][r] = 0.f;

    const int nk = Kdim >> 6;

    load_stage_h(sb, Ahi, Alo, Bhi, Kdim, m0, n0, 0, tid);
    cp_commit();
    load_stage_h(sb + H_STAGE, Ahi, Alo, Bhi, Kdim, m0, n0, 64, tid);
    cp_commit();

    for (int c = 0; c < nk; c++) {
        cp_wait1();
        __syncthreads();
        if (c + 2 < nk) {
            load_stage_h(sb + ((c + 2) % 3) * H_STAGE, Ahi, Alo, Bhi,
                         Kdim, m0, n0, (c + 2) << 6, tid);
        }
        cp_commit();

        const uint32_t st = sb + (c % 3) * H_STAGE;

#pragma unroll
        for (int ks = 0; ks < 4; ks++) {
            const int chunk = ks * 2 + lkc;
            uint32_t ah[2][4], al[2][4], bh[4][4];
#pragma unroll
            for (int mt = 0; mt < 2; mt++) {
                uint32_t off = (uint32_t)(arow[mt] * 128 + ((chunk ^ (arow[mt] & 7)) << 4));
                ldm4(ah[mt], st + H_AHI + off);
                ldm4(al[mt], st + H_ALO + off);
            }
#pragma unroll
            for (int nt = 0; nt < 4; nt++) {
                uint32_t off = (uint32_t)(brow[nt] * 128 + ((chunk ^ (brow[nt] & 7)) << 4));
                ldm4(bh[nt], st + H_BHI + off);
            }
#pragma unroll
            for (int mt = 0; mt < 2; mt++)
#pragma unroll
                for (int nt = 0; nt < 4; nt++)
#pragma unroll
                    for (int h = 0; h < 2; h++)
                        mma16816h(acc[mt][nt][h], ah[mt], bh[nt][h], bh[nt][h + 2]);
#pragma unroll
            for (int mt = 0; mt < 2; mt++)
#pragma unroll
                for (int nt = 0; nt < 4; nt++)
#pragma unroll
                    for (int h = 0; h < 2; h++)
                        mma16816h(acc[mt][nt][h], al[mt], bh[nt][h], bh[nt][h + 2]);
        }
    }

    const int qr = lane >> 2;
    const int qc = lane & 3;
#pragma unroll
    for (int mt = 0; mt < 2; mt++) {
#pragma unroll
        for (int nt = 0; nt < 4; nt++) {
#pragma unroll
            for (int h = 0; h < 2; h++) {
                int row = m0 + wm * 32 + mt * 16 + qr;
                int col = n0 + wn * 64 + nt * 16 + h * 8 + qc * 2;
                float* d = acc[mt][nt][h];
                *(float2*)(C + (size_t)row * Ndim + col)       = make_float2(d[0], d[1]);
                *(float2*)(C + (size_t)(row + 8) * Ndim + col) = make_float2(d[2], d[3]);
            }
        }
    }
}

// ============================================================
// RMSNorm + RoPE (table) -> bf16 hi/lo operand caches
// ============================================================
__global__ void __launch_bounds__(256) normrope_kernel(const int* __restrict__ segpos,
                                                       const int* __restrict__ curind,
                                                       const float* __restrict__ qns,
                                                       const float* __restrict__ kns)
{
    const int row  = blockIdx.x;
    const int slot = blockIdx.y;
    const int d    = threadIdx.x;
    const int b    = row / TT;
    const int t    = row - b * TT;

    const float* src;
    const float* sc;
    if (slot < NH) {
        src = g_qkv + (size_t)row * 4096 + slot * HD;
        sc  = qns;
    } else {
        src = g_qkv + (size_t)row * 4096 + 2048 + (slot - NH) * HD;
        sc  = kns;
    }

    float v  = src[d];
    float ss = v * v;
#pragma unroll
    for (int o = 16; o > 0; o >>= 1) ss += __shfl_xor_sync(0xffffffffu, ss, o);

    __shared__ float wsum[8];
    __shared__ float s_n[HD];
    __shared__ float s_r;
    if ((d & 31) == 0) wsum[d >> 5] = ss;
    __syncthreads();
    if (d == 0) {
        float tot = 0.f;
#pragma unroll
        for (int w = 0; w < 8; w++) tot += wsum[w];
        s_r = rsqrtf(tot * (1.0f / HD) + 1e-6f);
    }
    __syncthreads();

    float n = v * s_r * (1.0f + sc[d]);
    s_n[d] = n;
    __syncthreads();

    float2 sc2 = g_rope[(size_t)row * 128 + (d & 127)];
    float outv = (d < 128) ? (n * sc2.y - s_n[d + 128] * sc2.x)
                           : (n * sc2.y + s_n[d - 128] * sc2.x);

    if (slot < NH) {
        outv *= 0.0625f;   // fold HD^-1/2
        size_t o = ((size_t)(b * NH + slot) * TT + t) * HD + d;
        __nv_bfloat16 h = __float2bfloat16(outv);
        g_qhi[o] = h;
        g_qlo[o] = __float2bfloat16(outv - __bfloat162float(h));
    } else {
        int kv = slot - NH;
        int ct = curind[0] + t;
        size_t o = ((size_t)(b * NKV + kv) * SC + ct) * HD + d;
        __nv_bfloat16 h = __float2bfloat16(outv);
        g_khi[o] = h;
        g_klo[o] = __float2bfloat16(outv - __bfloat162float(h));
    }
}

// ============================================================
// HMMA windowed attention, double-buffered K/V chunk pipeline.
// Block: 64 queries x one (b,h); 256 threads = 8 warps.
// ============================================================
#define ATQ 64
#define ACK 32
// smem byte offsets
#define SQH 0                          // Q hi: 4 subtiles x 64 x 128B = 32768
#define SQL 32768
#define SKB0 65536                     // K stage: hi 16384 + lo 16384; x2 stages
#define SK_STRIDE 32768
#define SVB0 131072                    // V stage: hi 20480 + lo 20480; x2 stages
#define SV_STRIDE 40960
#define SPH 212992                     // P hi: 64 x 80B
#define SPL 218112
#define SPS 223232                     // psum[2][64] fp32
#define ATTN_SMEM 223744

__device__ __forceinline__ float capexp(float a, int pos, int s) {
    float e = __expf(a * 0.04f);                       // e^{2a/50}
    float t = 50.0f * __fdividef(e - 1.0f, e + 1.0f);  // 50*tanh(a/50)
    bool valid = (s <= pos) && (pos - s < WIN);
    return valid ? __expf(t) : 0.0f;
}

__device__ __forceinline__ void attn_load_chunk(char* sm, uint32_t sb, int buf,
                                                int s0, int bkv, int tid)
{
    const uint32_t kb = sb + SKB0 + buf * SK_STRIDE;
    const uint32_t ko = SKB0 + buf * SK_STRIDE;
    for (int i = tid; i < 32 * 32; i += 256) {
        int r = i >> 5, c = i & 31;
        int s = s0 + r;
        int sub = c >> 3, cc = c & 7;
        uint32_t so = (uint32_t)(sub * 4096 + r * 128 + ((cc ^ (r & 7)) << 4));
        if (s < SC) {
            size_t go = ((size_t)bkv * SC + s) * HD + c * 8;
            cpasync16(kb + so, g_khi + go);
            cpasync16(kb + 16384 + so, g_klo + go);
        } else {
            *(uint4*)(sm + ko + so)         = make_uint4(0, 0, 0, 0);
            *(uint4*)(sm + ko + 16384 + so) = make_uint4(0, 0, 0, 0);
        }
    }
    const uint32_t vb = sb + SVB0 + buf * SV_STRIDE;
    const uint32_t vo = SVB0 + buf * SV_STRIDE;
    for (int i = tid; i < 256 * 4; i += 256) {
        int dd = i >> 2, c = i & 3;
        uint32_t so = (uint32_t)(dd * 80 + c * 16);
        if (s0 + c * 8 + 7 < SC) {
            size_t go = ((size_t)bkv * HD + dd) * SC + s0 + c * 8;
            cpasync16(vb + so, g_vthi + go);
            cpasync16(vb + 20480 + so, g_vtlo + go);
        } else {
            *(uint4*)(sm + vo + so)         = make_uint4(0, 0, 0, 0);
            *(uint4*)(sm + vo + 20480 + so) = make_uint4(0, 0, 0, 0);
        }
    }
}

__global__ void __launch_bounds__(256) attn_mma(const int* __restrict__ segpos)
{
    extern __shared__ __align__(128) char sm[];
    const uint32_t sb = s2u(sm);
    const int tid  = threadIdx.x;
    const int wid  = tid >> 5;
    const int lane = tid & 31;
    const int t0   = blockIdx.x * ATQ;
    const int head = blockIdx.y;
    const int b    = blockIdx.z;
    const int kv   = head / GRP;
    const int bkv  = b * NKV + kv;
    const int wm   = wid >> 1;
    const int wh   = wid & 1;
    const int lrow = lane & 15;
    const int lkc  = lane >> 4;
    const int qr   = lane >> 2;
    const int qc   = lane & 3;

    float* psum = (float*)(sm + SPS);

    int minp, maxp;
    {
        const int* sp = segpos + b * TT + t0;
        minp = sp[0]; maxp = sp[0];
#pragma unroll 8
        for (int i = 1; i < ATQ; i++) {
            int p = sp[i];
            minp = min(minp, p);
            maxp = max(maxp, p);
        }
    }
    const int smin = max(0, minp - (WIN - 1)) & ~31;
    const int smax = min(SC - 1, maxp);
    const int nchunks = ((smax - smin) >> 5) + 1;

    const int myp0 = segpos[b * TT + t0 + wm * 16 + qr];
    const int myp1 = segpos[b * TT + t0 + wm * 16 + qr + 8];

    if (tid < 2 * ATQ) psum[tid] = 0.f;

    // prologue: Q tile + chunk 0  (one commit group)
    {
        const __nv_bfloat16* gh = g_qhi + ((size_t)(b * NH + head) * TT + t0) * HD;
        const __nv_bfloat16* gl = g_qlo + ((size_t)(b * NH + head) * TT + t0) * HD;
        for (int i = tid; i < ATQ * 32; i += 256) {
            int r = i >> 5, c = i & 31;
            int sub = c >> 3, cc = c & 7;
            uint32_t so = (uint32_t)(sub * 8192 + r * 128 + ((cc ^ (r & 7)) << 4));
            cpasync16(sb + SQH + so, gh + (size_t)r * HD + c * 8);
            cpasync16(sb + SQL + so, gl + (size_t)r * HD + c * 8);
        }
        attn_load_chunk(sm, sb, 0, smin, bkv, tid);
    }
    cp_commit();

    float oacc[16][4];
#pragma unroll
    for (int i = 0; i < 16; i++)
#pragma unroll
        for (int r = 0; r < 4; r++) oacc[i][r] = 0.f;

    for (int ci = 0; ci < nchunks; ci++) {
        const int s0 = smin + ci * ACK;
        __syncthreads();
        if (ci + 1 < nchunks)
            attn_load_chunk(sm, sb, (ci + 1) & 1, s0 + ACK, bkv, tid);
        cp_commit();
        cp_wait1();
        __syncthreads();

        const uint32_t kb = sb + SKB0 + (ci & 1) * SK_STRIDE;
        const uint32_t vb = sb + SVB0 + (ci & 1) * SV_STRIDE;

        // ---- QK^T : m16 x n16 per warp, k = 256 ----
        float sacc[2][4];
#pragma unroll
        for (int hh = 0; hh < 2; hh++)
#pragma unroll
            for (int r = 0; r < 4; r++) sacc[hh][r] = 0.f;

        const int arow = wm * 16 + lrow;
        const int brow = wh * 16 + lrow;
#pragma unroll
        for (int ks = 0; ks < 16; ks++) {
            int sub = ks >> 2, cc = (ks & 3) * 2 + lkc;
            uint32_t ao = (uint32_t)(sub * 8192 + arow * 128 + ((cc ^ (arow & 7)) << 4));
            uint32_t bo = (uint32_t)(sub * 4096 + brow * 128 + ((cc ^ (brow & 7)) << 4));
            uint32_t ah[4], al[4], bh[4], bl[4];
            ldm4(ah, sb + SQH + ao);
            ldm4(al, sb + SQL + ao);
            ldm4(bh, kb + bo);
            ldm4(bl, kb + 16384 + bo);
#pragma unroll
            for (int hh = 0; hh < 2; hh++) mma16816(sacc[hh], ah, bh[hh], bh[hh + 2]);
#pragma unroll
            for (int hh = 0; hh < 2; hh++) mma16816(sacc[hh], ah, bl[hh], bl[hh + 2]);
#pragma unroll
            for (int hh = 0; hh < 2; hh++) mma16816(sacc[hh], al, bh[hh], bh[hh + 2]);
        }

        // ---- softcap + mask + exp; write P hi/lo; partial row sums ----
        float rs0 = 0.f, rs1 = 0.f;
#pragma unroll
        for (int hh = 0; hh < 2; hh++) {
            int colL = wh * 16 + hh * 8 + 2 * qc;
            int colG = s0 + colL;
            float p00 = capexp(sacc[hh][0], myp0, colG);
            float p01 = capexp(sacc[hh][1], myp0, colG + 1);
            float p10 = capexp(sacc[hh][2], myp1, colG);
            float p11 = capexp(sacc[hh][3], myp1, colG + 1);
            rs0 += p00 + p01;
            rs1 += p10 + p11;
            __nv_bfloat162 lo0, lo1;
            __nv_bfloat162 hi0 = split_pack_hi(p00, p01, &lo0);
            __nv_bfloat162 hi1 = split_pack_hi(p10, p11, &lo1);
            int r0 = wm * 16 + qr;
            uint32_t o0 = (uint32_t)(r0 * 80 + colL * 2);
            uint32_t o1 = o0 + 8 * 80;
            *(__nv_bfloat162*)(sm + SPH + o0) = hi0;
            *(__nv_bfloat162*)(sm + SPL + o0) = lo0;
            *(__nv_bfloat162*)(sm + SPH + o1) = hi1;
            *(__nv_bfloat162*)(sm + SPL + o1) = lo1;
        }
        rs0 += __shfl_xor_sync(0xffffffffu, rs0, 1);
        rs0 += __shfl_xor_sync(0xffffffffu, rs0, 2);
        rs1 += __shfl_xor_sync(0xffffffffu, rs1, 1);
        rs1 += __shfl_xor_sync(0xffffffffu, rs1, 2);
        if (qc == 0) {
            psum[wh * 64 + wm * 16 + qr]     += rs0;
            psum[wh * 64 + wm * 16 + qr + 8] += rs1;
        }
        __syncthreads();

        // ---- P @ V : m16 x d128 per warp, k = 32 ----
        const int prow = wm * 16 + lrow;
#pragma unroll
        for (int ks2 = 0; ks2 < 2; ks2++) {
            uint32_t po = (uint32_t)(prow * 80 + ((ks2 * 2 + lkc) << 4));
            uint32_t ph[4], pl[4];
            ldm4(ph, sb + SPH + po);
            ldm4(pl, sb + SPL + po);
            uint32_t vh4[8][4], vl4[8][4];
#pragma unroll
            for (int nt = 0; nt < 8; nt++) {
                int vrow = wh * 128 + nt * 16 + lrow;
                uint32_t vo = (uint32_t)(vrow * 80 + ((ks2 * 2 + lkc) << 4));
                ldm4(vh4[nt], vb + vo);
                ldm4(vl4[nt], vb + 20480 + vo);
            }
#pragma unroll
            for (int nt = 0; nt < 8; nt++)
#pragma unroll
                for (int hh = 0; hh < 2; hh++)
                    mma16816(oacc[nt * 2 + hh], ph, vh4[nt][hh], vh4[nt][hh + 2]);
#pragma unroll
            for (int nt = 0; nt < 8; nt++)
#pragma unroll
                for (int hh = 0; hh < 2; hh++)
                    mma16816(oacc[nt * 2 + hh], ph, vl4[nt][hh], vl4[nt][hh + 2]);
#pragma unroll
            for (int nt = 0; nt < 8; nt++)
#pragma unroll
                for (int hh = 0; hh < 2; hh++)
                    mma16816(oacc[nt * 2 + hh], pl, vh4[nt][hh], vh4[nt][hh + 2]);
        }
    }

    // ---- epilogue: divide by row sums, write fp16 hi/lo for O-proj ----
    const int r0 = wm * 16 + qr;
    const float inv0 = __fdividef(1.0f, psum[r0] + psum[64 + r0]);
    const float inv1 = __fdividef(1.0f, psum[r0 + 8] + psum[64 + r0 + 8]);
    const size_t tok0 = (size_t)(b * TT + t0 + r0);
#pragma unroll
    for (int nt = 0; nt < 8; nt++) {
#pragma unroll
        for (int hh = 0; hh < 2; hh++) {
            int col = head * HD + wh * 128 + nt * 16 + hh * 8 + 2 * qc;
            float* d = oacc[nt * 2 + hh];
            __half2 lo0, lo1;
            __half2 hi0 = split_pack_hi_h(d[0] * inv0, d[1] * inv0, &lo0);
            __half2 hi1 = split_pack_hi_h(d[2] * inv1, d[3] * inv1, &lo1);
            *(__half2*)(g_ahi + tok0 * 2048 + col)       = hi0;
            *(__half2*)(g_alo + tok0 * 2048 + col)       = lo0;
            *(__half2*)(g_ahi + (tok0 + 8) * 2048 + col) = hi1;
            *(__half2*)(g_alo + (tok0 + 8) * 2048 + col) = lo1;
        }
    }
}

// ============================================================
// Launch (profiler captures launch index 3 -> QKV GEMM)
//   0: convert_split   1: transpose(wq)   2: transpose2(wk,wv)
//   3: QKV GEMM  <- profiled   4: rope_table   5: transpose_h(wo)
//   6: normrope   7: vtrans   8: attn   9: O GEMM (fp16 x2)
// ============================================================
extern "C" void kernel_launch(void* const* d_in, const int* in_sizes, int n_in,
                              void* d_out, int out_size)
{
    const float* x      = (const float*)d_in[0];
    const int*   segpos = (const int*)  d_in[1];
    const int*   curind = (const int*)  d_in[2];
    const float* wq     = (const float*)d_in[3];
    const float* wk     = (const float*)d_in[4];
    const float* wv     = (const float*)d_in[5];
    const float* wo     = (const float*)d_in[6];
    const float* qns    = (const float*)d_in[7];
    const float* kns    = (const float*)d_in[8];
    float* out = (float*)d_out;

    float* gqkv;
    __nv_bfloat16 *xhi, *xlo, *wthi, *wtlo;
    __half *ahi, *alo, *wohi;
    cudaGetSymbolAddress((void**)&gqkv, g_qkv);
    cudaGetSymbolAddress((void**)&xhi,  g_xhi);
    cudaGetSymbolAddress((void**)&xlo,  g_xlo);
    cudaGetSymbolAddress((void**)&ahi,  g_ahi);
    cudaGetSymbolAddress((void**)&alo,  g_alo);
    cudaGetSymbolAddress((void**)&wthi, g_wthi);
    cudaGetSymbolAddress((void**)&wtlo, g_wtlo);
    cudaGetSymbolAddress((void**)&wohi, g_wohi);

    cudaFuncSetAttribute(gemm_bf16x3, cudaFuncAttributeMaxDynamicSharedMemorySize, GEMM_SMEM);
    cudaFuncSetAttribute(gemm_fp16x2, cudaFuncAttributeMaxDynamicSharedMemorySize, GEMMH_SMEM);
    cudaFuncSetAttribute(attn_mma, cudaFuncAttributeMaxDynamicSharedMemorySize, ATTN_SMEM);

    // 0) split x into bf16 hi/lo
    {
        int n4 = (MM * DD) / 4;
        convert_split<<<n4 / 256, 256>>>((const float4*)x,
                                         (__nv_bfloat162*)xhi, (__nv_bfloat162*)xlo, n4);
    }
    // 1-2) transpose + split q/k/v weights
    transpose_split<<<dim3(DD / 32, DD / 32), dim3(32, 8)>>>(wq, wthi + WQ_OFF, wtlo + WQ_OFF, DD, DD);
    transpose_split2<<<dim3(2 * (NKV * HD) / 32, DD / 32), dim3(32, 8)>>>(
        wk, wv, wthi + WK_OFF, wtlo + WK_OFF, wthi + WV_OFF, wtlo + WV_OFF, DD, NKV * HD);

    // 3) fused QKV projection  <- profiled launch
    gemm_bf16x3<<<dim3(4096 / 128, MM / 128), 256, GEMM_SMEM>>>(
        xhi, xlo, wthi, wtlo, gqkv, 4096, DD);

    // 4) rope table ; 5) wo transpose (fp16 hi)
    rope_table<<<(MM * 128) / 256, 256>>>(segpos);
    transpose_h<<<dim3(DD / 32, (NH * HD) / 32), dim3(32, 8)>>>(wo, wohi, NH * HD, DD);

    // 6-7) norm + rope -> bf16 hi/lo q + k-cache ; v transpose -> vt cache
    normrope_kernel<<<dim3(MM, NH + NKV), 256>>>(segpos, curind, qns, kns);
    vtrans_kernel<<<dim3(TT / 32, HD / 32, BB * NKV), dim3(32, 8)>>>(curind);

    // 8) HMMA attention -> g_ahi/g_alo (fp16)
    attn_mma<<<dim3(TT / ATQ, NH, BB), 256, ATTN_SMEM>>>(segpos);

    // 9) output projection (fp16 2-product) -> d_out
    gemm_fp16x2<<<dim3(DD / 128, MM / 128), 256, GEMMH_SMEM>>>(
        ahi, alo, wohi, out, DD, NH * HD);
}

// round 14
// speedup vs baseline: 1.3832x; 1.2284x over previous
#include <cuda_runtime.h>
#include <cuda_bf16.h>
#include <cuda_fp16.h>
#include <math.h>
#include <cstdint>

// ---- problem constants ----
#define BB   2
#define TT   2048
#define DD   2048
#define NH   8
#define NKV  4
#define HD   256
#define SC   2048
#define WIN  512
#define GRP  (NH / NKV)   // 2
#define MM   (BB * TT)    // 4096

// ---- device scratch ----
__device__ float g_qkv[(size_t)MM * 4096];              // fused projection output (fp32)
__device__ float2 g_rope[(size_t)MM * 128];             // per-(row, i) sin/cos

// x split, fp16 hi/lo (A-operand of QKV projection)
__device__ __half g_xhi[(size_t)MM * DD], g_xlo[(size_t)MM * DD];
// attention output, fp16 hi/lo (A-operand of O projection)
__device__ __half g_ahi[(size_t)MM * NH * HD], g_alo[(size_t)MM * NH * HD];

// attention operand caches, bf16 hi/lo
__device__ __nv_bfloat16 g_qhi[(size_t)BB * NH * TT * HD], g_qlo[(size_t)BB * NH * TT * HD];
__device__ __nv_bfloat16 g_khi[(size_t)BB * NKV * SC * HD], g_klo[(size_t)BB * NKV * SC * HD];
__device__ __nv_bfloat16 g_vthi[(size_t)BB * NKV * HD * SC], g_vtlo[(size_t)BB * NKV * HD * SC];

// weights transposed [N,K], fp16 hi only. rows: wq [0,2048), wk [2048,3072), wv [3072,4096)
__device__ __half g_wqkv[(size_t)4096 * DD];
__device__ __half g_wohi[(size_t)DD * DD];              // wo transposed [N,K], fp16 hi

// ============================================================
// helpers
// ============================================================
__device__ __forceinline__ uint32_t s2u(const void* p) {
    uint32_t a;
    asm("{ .reg .u64 t; cvta.to.shared.u64 t, %1; cvt.u32.u64 %0, t; }" : "=r"(a) : "l"(p));
    return a;
}
__device__ __forceinline__ void cpasync16(uint32_t saddr, const void* gaddr) {
    asm volatile("cp.async.cg.shared.global [%0], [%1], 16;" :: "r"(saddr), "l"(gaddr));
}
__device__ __forceinline__ void cp_commit() {
    asm volatile("cp.async.commit_group;" ::: "memory");
}
__device__ __forceinline__ void cp_wait1() {
    asm volatile("cp.async.wait_group 1;" ::: "memory");
}
__device__ __forceinline__ void cp_wait0() {
    asm volatile("cp.async.wait_group 0;" ::: "memory");
}
__device__ __forceinline__ void ldm4(uint32_t* d, uint32_t addr) {
    asm volatile("ldmatrix.sync.aligned.m8n8.x4.shared.b16 {%0,%1,%2,%3}, [%4];"
                 : "=r"(d[0]), "=r"(d[1]), "=r"(d[2]), "=r"(d[3]) : "r"(addr));
}
__device__ __forceinline__ void mma16816(float* c, const uint32_t* a, uint32_t b0, uint32_t b1) {
    asm volatile("mma.sync.aligned.m16n8k16.row.col.f32.bf16.bf16.f32 "
                 "{%0,%1,%2,%3}, {%4,%5,%6,%7}, {%8,%9}, {%0,%1,%2,%3};"
                 : "+f"(c[0]), "+f"(c[1]), "+f"(c[2]), "+f"(c[3])
                 : "r"(a[0]), "r"(a[1]), "r"(a[2]), "r"(a[3]), "r"(b0), "r"(b1));
}
__device__ __forceinline__ void mma16816h(float* c, const uint32_t* a, uint32_t b0, uint32_t b1) {
    asm volatile("mma.sync.aligned.m16n8k16.row.col.f32.f16.f16.f32 "
                 "{%0,%1,%2,%3}, {%4,%5,%6,%7}, {%8,%9}, {%0,%1,%2,%3};"
                 : "+f"(c[0]), "+f"(c[1]), "+f"(c[2]), "+f"(c[3])
                 : "r"(a[0]), "r"(a[1]), "r"(a[2]), "r"(a[3]), "r"(b0), "r"(b1));
}
__device__ __forceinline__ __nv_bfloat162 split_pack_hi(float a, float b,
                                                        __nv_bfloat162* lo) {
    __nv_bfloat16 ha = __float2bfloat16(a), hb = __float2bfloat16(b);
    *lo = __halves2bfloat162(__float2bfloat16(a - __bfloat162float(ha)),
                             __float2bfloat16(b - __bfloat162float(hb)));
    return __halves2bfloat162(ha, hb);
}
__device__ __forceinline__ __half2 split_pack_hi_h(float a, float b, __half2* lo) {
    __half ha = __float2half_rn(a), hb = __float2half_rn(b);
    *lo = __halves2half2(__float2half_rn(a - __half2float(ha)),
                         __float2half_rn(b - __half2float(hb)));
    return __halves2half2(ha, hb);
}

// ============================================================
// convert: fp32 -> (hi, lo) fp16 pair, vectorized x4
// ============================================================
__global__ void __launch_bounds__(256) convert_split_h(const float4* __restrict__ src,
                                                       __half2* __restrict__ hi,
                                                       __half2* __restrict__ lo,
                                                       int n4)
{
    int i = blockIdx.x * 256 + threadIdx.x;
    if (i >= n4) return;
    float4 v = src[i];
    __half2 l0, l1;
    __half2 h0 = split_pack_hi_h(v.x, v.y, &l0);
    __half2 h1 = split_pack_hi_h(v.z, v.w, &l1);
    hi[2 * i] = h0; hi[2 * i + 1] = h1;
    lo[2 * i] = l0; lo[2 * i + 1] = l1;
}

// ============================================================
// transpose to fp16 (hi only): W[K,N] fp32 -> Wt [N,K] fp16
// ============================================================
__global__ void __launch_bounds__(256) transpose_h(const float* __restrict__ W,
                                                   __half* __restrict__ Th,
                                                   int K, int N)
{
    __shared__ float s[32][33];
    int n0 = blockIdx.x * 32, k0 = blockIdx.y * 32;
    for (int i = threadIdx.y; i < 32; i += 8)
        s[i][threadIdx.x] = W[(size_t)(k0 + i) * N + n0 + threadIdx.x];
    __syncthreads();
    for (int i = threadIdx.y; i < 32; i += 8) {
        size_t o = (size_t)(n0 + i) * K + k0 + threadIdx.x;
        Th[o] = __float2half_rn(s[threadIdx.x][i]);
    }
}

// fused two-tensor variant (wk, wv)
__global__ void __launch_bounds__(256) transpose_h2(const float* __restrict__ Wa,
                                                    const float* __restrict__ Wb,
                                                    __half* __restrict__ Tha,
                                                    __half* __restrict__ Thb,
                                                    int K, int N)
{
    __shared__ float s[32][33];
    const int nb = N / 32;
    const bool second = (blockIdx.x >= nb);
    const float* W = second ? Wb : Wa;
    __half* Th = second ? Thb : Tha;
    int n0 = (second ? blockIdx.x - nb : blockIdx.x) * 32;
    int k0 = blockIdx.y * 32;
    for (int i = threadIdx.y; i < 32; i += 8)
        s[i][threadIdx.x] = W[(size_t)(k0 + i) * N + n0 + threadIdx.x];
    __syncthreads();
    for (int i = threadIdx.y; i < 32; i += 8) {
        size_t o = (size_t)(n0 + i) * K + k0 + threadIdx.x;
        Th[o] = __float2half_rn(s[threadIdx.x][i]);
    }
}

// ============================================================
// RoPE sin/cos table: per (row, i<128)
// ============================================================
__global__ void __launch_bounds__(256) rope_table(const int* __restrict__ segpos)
{
    int idx = blockIdx.x * 256 + threadIdx.x;       // MM*128 total
    int row = idx >> 7, i = idx & 127;
    float pos = (float)segpos[row];
    float ts  = exp2f((float)i * (13.287712379549449f / 128.0f));
    float sv, cv;
    sincosf(pos / ts, &sv, &cv);
    g_rope[idx] = make_float2(sv, cv);
}

// ============================================================
// V transpose + split
// ============================================================
__global__ void __launch_bounds__(256) vtrans_kernel(const int* __restrict__ curind)
{
    __shared__ float s[32][33];
    int t0 = blockIdx.x * 32, d0 = blockIdx.y * 32;
    int bkv = blockIdx.z;
    int b = bkv / NKV, kv = bkv - b * NKV;
    int tx = threadIdx.x, ty = threadIdx.y;
    for (int i = ty; i < 32; i += 8)
        s[i][tx] = g_qkv[(size_t)(b * TT + t0 + i) * 4096 + 3072 + kv * HD + d0 + tx];
    __syncthreads();
    int s0 = curind[0] + t0;
    for (int i = ty; i < 32; i += 8) {
        float v = s[tx][i];
        __nv_bfloat16 h = __float2bfloat16(v);
        size_t o = ((size_t)bkv * HD + d0 + i) * SC + s0 + tx;
        g_vthi[o] = h;
        g_vtlo[o] = __float2bfloat16(v - __bfloat162float(h));
    }
}

// ============================================================
// HMMA GEMM fp16 x2-product: C = (Ahi+Alo)[M,K] @ Bhi[N,K]^T
// 128x128 CTA tile, BK=64, 2-stage cp.async, 8 warps (4x2),
// warp 32x64, 48KB/stage -> 96KB smem -> 2 CTAs/SM.
// ============================================================
#define H_AHI 0
#define H_ALO 16384
#define H_BHI 32768
#define H_STAGE 49152
#define GEMMH_SMEM (2 * H_STAGE)            // 98304

__device__ __forceinline__ void load_stage_h(uint32_t sbase,
    const __half* __restrict__ Ahi, const __half* __restrict__ Alo,
    const __half* __restrict__ Bhi,
    int Kdim, int m0, int n0, int k0, int tid)
{
#pragma unroll
    for (int ii = 0; ii < 4; ii++) {
        int i = tid + ii * 256;
        int r = i >> 3, c = i & 7;
        uint32_t so = (uint32_t)(r * 128 + ((c ^ (r & 7)) << 4));
        size_t goA = (size_t)(m0 + r) * Kdim + k0 + c * 8;
        size_t goB = (size_t)(n0 + r) * Kdim + k0 + c * 8;
        cpasync16(sbase + H_AHI + so, Ahi + goA);
        cpasync16(sbase + H_ALO + so, Alo + goA);
        cpasync16(sbase + H_BHI + so, Bhi + goB);
    }
}

__global__ void __launch_bounds__(256, 2) gemm_fp16x2(
    const __half* __restrict__ Ahi, const __half* __restrict__ Alo,
    const __half* __restrict__ Bhi,
    float* __restrict__ C, int Ndim, int Kdim)
{
    extern __shared__ __align__(128) char smem[];
    const uint32_t sb = s2u(smem);
    const int tid  = threadIdx.x;
    const int wid  = tid >> 5;
    const int lane = tid & 31;
    const int wm   = wid >> 1;
    const int wn   = wid & 1;
    const int m0   = blockIdx.y * 128;
    const int n0   = blockIdx.x * 128;

    const int lrow = lane & 15;
    const int lkc  = lane >> 4;

    int arow[2], brow[4];
#pragma unroll
    for (int mt = 0; mt < 2; mt++) arow[mt] = wm * 32 + mt * 16 + lrow;
#pragma unroll
    for (int nt = 0; nt < 4; nt++) brow[nt] = wn * 64 + nt * 16 + lrow;

    float acc[2][4][2][4];
#pragma unroll
    for (int mt = 0; mt < 2; mt++)
#pragma unroll
        for (int nt = 0; nt < 4; nt++)
#pragma unroll
            for (int h = 0; h < 2; h++)
#pragma unroll
                for (int r = 0; r < 4; r++) acc[mt][nt][h][r] = 0.f;

    const int nk = Kdim >> 6;

    load_stage_h(sb, Ahi, Alo, Bhi, Kdim, m0, n0, 0, tid);
    cp_commit();

    for (int c = 0; c < nk; c++) {
        if (c + 1 < nk) {
            load_stage_h(sb + ((c + 1) & 1) * H_STAGE, Ahi, Alo, Bhi,
                         Kdim, m0, n0, (c + 1) << 6, tid);
            cp_commit();
            cp_wait1();
        } else {
            cp_wait0();
        }
        __syncthreads();

        const uint32_t st = sb + (c & 1) * H_STAGE;

#pragma unroll
        for (int ks = 0; ks < 4; ks++) {
            const int chunk = ks * 2 + lkc;
            uint32_t ah[2][4], al[2][4], bh[4][4];
#pragma unroll
            for (int mt = 0; mt < 2; mt++) {
                uint32_t off = (uint32_t)(arow[mt] * 128 + ((chunk ^ (arow[mt] & 7)) << 4));
                ldm4(ah[mt], st + H_AHI + off);
                ldm4(al[mt], st + H_ALO + off);
            }
#pragma unroll
            for (int nt = 0; nt < 4; nt++) {
                uint32_t off = (uint32_t)(brow[nt] * 128 + ((chunk ^ (brow[nt] & 7)) << 4));
                ldm4(bh[nt], st + H_BHI + off);
            }
#pragma unroll
            for (int mt = 0; mt < 2; mt++)
#pragma unroll
                for (int nt = 0; nt < 4; nt++)
#pragma unroll
                    for (int h = 0; h < 2; h++)
                        mma16816h(acc[mt][nt][h], ah[mt], bh[nt][h], bh[nt][h + 2]);
#pragma unroll
            for (int mt = 0; mt < 2; mt++)
#pragma unroll
                for (int nt = 0; nt < 4; nt++)
#pragma unroll
                    for (int h = 0; h < 2; h++)
                        mma16816h(acc[mt][nt][h], al[mt], bh[nt][h], bh[nt][h + 2]);
        }
        __syncthreads();
    }

    const int qr = lane >> 2;
    const int qc = lane & 3;
#pragma unroll
    for (int mt = 0; mt < 2; mt++) {
#pragma unroll
        for (int nt = 0; nt < 4; nt++) {
#pragma unroll
            for (int h = 0; h < 2; h++) {
                int row = m0 + wm * 32 + mt * 16 + qr;
                int col = n0 + wn * 64 + nt * 16 + h * 8 + qc * 2;
                float* d = acc[mt][nt][h];
                *(float2*)(C + (size_t)row * Ndim + col)       = make_float2(d[0], d[1]);
                *(float2*)(C + (size_t)(row + 8) * Ndim + col) = make_float2(d[2], d[3]);
            }
        }
    }
}

// ============================================================
// RMSNorm + RoPE (table) -> bf16 hi/lo operand caches
// ============================================================
__global__ void __launch_bounds__(256) normrope_kernel(const int* __restrict__ segpos,
                                                       const int* __restrict__ curind,
                                                       const float* __restrict__ qns,
                                                       const float* __restrict__ kns)
{
    const int row  = blockIdx.x;
    const int slot = blockIdx.y;
    const int d    = threadIdx.x;
    const int b    = row / TT;
    const int t    = row - b * TT;

    const float* src;
    const float* sc;
    if (slot < NH) {
        src = g_qkv + (size_t)row * 4096 + slot * HD;
        sc  = qns;
    } else {
        src = g_qkv + (size_t)row * 4096 + 2048 + (slot - NH) * HD;
        sc  = kns;
    }

    float v  = src[d];
    float ss = v * v;
#pragma unroll
    for (int o = 16; o > 0; o >>= 1) ss += __shfl_xor_sync(0xffffffffu, ss, o);

    __shared__ float wsum[8];
    __shared__ float s_n[HD];
    __shared__ float s_r;
    if ((d & 31) == 0) wsum[d >> 5] = ss;
    __syncthreads();
    if (d == 0) {
        float tot = 0.f;
#pragma unroll
        for (int w = 0; w < 8; w++) tot += wsum[w];
        s_r = rsqrtf(tot * (1.0f / HD) + 1e-6f);
    }
    __syncthreads();

    float n = v * s_r * (1.0f + sc[d]);
    s_n[d] = n;
    __syncthreads();

    float2 sc2 = g_rope[(size_t)row * 128 + (d & 127)];
    float outv = (d < 128) ? (n * sc2.y - s_n[d + 128] * sc2.x)
                           : (n * sc2.y + s_n[d - 128] * sc2.x);

    if (slot < NH) {
        outv *= 0.0625f;   // fold HD^-1/2
        size_t o = ((size_t)(b * NH + slot) * TT + t) * HD + d;
        __nv_bfloat16 h = __float2bfloat16(outv);
        g_qhi[o] = h;
        g_qlo[o] = __float2bfloat16(outv - __bfloat162float(h));
    } else {
        int kv = slot - NH;
        int ct = curind[0] + t;
        size_t o = ((size_t)(b * NKV + kv) * SC + ct) * HD + d;
        __nv_bfloat16 h = __float2bfloat16(outv);
        g_khi[o] = h;
        g_klo[o] = __float2bfloat16(outv - __bfloat162float(h));
    }
}

// ============================================================
// HMMA windowed attention, double-buffered K/V chunk pipeline.
// Block: 64 queries x one (b,h); 256 threads = 8 warps.
// ============================================================
#define ATQ 64
#define ACK 32
// smem byte offsets
#define SQH 0                          // Q hi: 4 subtiles x 64 x 128B = 32768
#define SQL 32768
#define SKB0 65536                     // K stage: hi 16384 + lo 16384; x2 stages
#define SK_STRIDE 32768
#define SVB0 131072                    // V stage: hi 20480 + lo 20480; x2 stages
#define SV_STRIDE 40960
#define SPH 212992                     // P hi: 64 x 80B
#define SPL 218112
#define SPS 223232                     // psum[2][64] fp32
#define ATTN_SMEM 223744

__device__ __forceinline__ float capexp(float a, int pos, int s) {
    float e = __expf(a * 0.04f);                       // e^{2a/50}
    float t = 50.0f * __fdividef(e - 1.0f, e + 1.0f);  // 50*tanh(a/50)
    bool valid = (s <= pos) && (pos - s < WIN);
    return valid ? __expf(t) : 0.0f;
}

__device__ __forceinline__ void attn_load_chunk(char* sm, uint32_t sb, int buf,
                                                int s0, int bkv, int tid)
{
    const uint32_t kb = sb + SKB0 + buf * SK_STRIDE;
    const uint32_t ko = SKB0 + buf * SK_STRIDE;
    for (int i = tid; i < 32 * 32; i += 256) {
        int r = i >> 5, c = i & 31;
        int s = s0 + r;
        int sub = c >> 3, cc = c & 7;
        uint32_t so = (uint32_t)(sub * 4096 + r * 128 + ((cc ^ (r & 7)) << 4));
        if (s < SC) {
            size_t go = ((size_t)bkv * SC + s) * HD + c * 8;
            cpasync16(kb + so, g_khi + go);
            cpasync16(kb + 16384 + so, g_klo + go);
        } else {
            *(uint4*)(sm + ko + so)         = make_uint4(0, 0, 0, 0);
            *(uint4*)(sm + ko + 16384 + so) = make_uint4(0, 0, 0, 0);
        }
    }
    const uint32_t vb = sb + SVB0 + buf * SV_STRIDE;
    const uint32_t vo = SVB0 + buf * SV_STRIDE;
    for (int i = tid; i < 256 * 4; i += 256) {
        int dd = i >> 2, c = i & 3;
        uint32_t so = (uint32_t)(dd * 80 + c * 16);
        if (s0 + c * 8 + 7 < SC) {
            size_t go = ((size_t)bkv * HD + dd) * SC + s0 + c * 8;
            cpasync16(vb + so, g_vthi + go);
            cpasync16(vb + 20480 + so, g_vtlo + go);
        } else {
            *(uint4*)(sm + vo + so)         = make_uint4(0, 0, 0, 0);
            *(uint4*)(sm + vo + 20480 + so) = make_uint4(0, 0, 0, 0);
        }
    }
}

__global__ void __launch_bounds__(256) attn_mma(const int* __restrict__ segpos)
{
    extern __shared__ __align__(128) char sm[];
    const uint32_t sb = s2u(sm);
    const int tid  = threadIdx.x;
    const int wid  = tid >> 5;
    const int lane = tid & 31;
    const int t0   = blockIdx.x * ATQ;
    const int head = blockIdx.y;
    const int b    = blockIdx.z;
    const int kv   = head / GRP;
    const int bkv  = b * NKV + kv;
    const int wm   = wid >> 1;
    const int wh   = wid & 1;
    const int lrow = lane & 15;
    const int lkc  = lane >> 4;
    const int qr   = lane >> 2;
    const int qc   = lane & 3;

    float* psum = (float*)(sm + SPS);

    int minp, maxp;
    {
        const int* sp = segpos + b * TT + t0;
        minp = sp[0]; maxp = sp[0];
#pragma unroll 8
        for (int i = 1; i < ATQ; i++) {
            int p = sp[i];
            minp = min(minp, p);
            maxp = max(maxp, p);
        }
    }
    const int smin = max(0, minp - (WIN - 1)) & ~31;
    const int smax = min(SC - 1, maxp);
    const int nchunks = ((smax - smin) >> 5) + 1;

    const int myp0 = segpos[b * TT + t0 + wm * 16 + qr];
    const int myp1 = segpos[b * TT + t0 + wm * 16 + qr + 8];

    if (tid < 2 * ATQ) psum[tid] = 0.f;

    // prologue: Q tile + chunk 0  (one commit group)
    {
        const __nv_bfloat16* gh = g_qhi + ((size_t)(b * NH + head) * TT + t0) * HD;
        const __nv_bfloat16* gl = g_qlo + ((size_t)(b * NH + head) * TT + t0) * HD;
        for (int i = tid; i < ATQ * 32; i += 256) {
            int r = i >> 5, c = i & 31;
            int sub = c >> 3, cc = c & 7;
            uint32_t so = (uint32_t)(sub * 8192 + r * 128 + ((cc ^ (r & 7)) << 4));
            cpasync16(sb + SQH + so, gh + (size_t)r * HD + c * 8);
            cpasync16(sb + SQL + so, gl + (size_t)r * HD + c * 8);
        }
        attn_load_chunk(sm, sb, 0, smin, bkv, tid);
    }
    cp_commit();

    float oacc[16][4];
#pragma unroll
    for (int i = 0; i < 16; i++)
#pragma unroll
        for (int r = 0; r < 4; r++) oacc[i][r] = 0.f;

    for (int ci = 0; ci < nchunks; ci++) {
        const int s0 = smin + ci * ACK;
        __syncthreads();
        if (ci + 1 < nchunks)
            attn_load_chunk(sm, sb, (ci + 1) & 1, s0 + ACK, bkv, tid);
        cp_commit();
        cp_wait1();
        __syncthreads();

        const uint32_t kb = sb + SKB0 + (ci & 1) * SK_STRIDE;
        const uint32_t vb = sb + SVB0 + (ci & 1) * SV_STRIDE;

        // ---- QK^T : m16 x n16 per warp, k = 256 ----
        float sacc[2][4];
#pragma unroll
        for (int hh = 0; hh < 2; hh++)
#pragma unroll
            for (int r = 0; r < 4; r++) sacc[hh][r] = 0.f;

        const int arow = wm * 16 + lrow;
        const int brow = wh * 16 + lrow;
#pragma unroll
        for (int ks = 0; ks < 16; ks++) {
            int sub = ks >> 2, cc = (ks & 3) * 2 + lkc;
            uint32_t ao = (uint32_t)(sub * 8192 + arow * 128 + ((cc ^ (arow & 7)) << 4));
            uint32_t bo = (uint32_t)(sub * 4096 + brow * 128 + ((cc ^ (brow & 7)) << 4));
            uint32_t ah[4], al[4], bh[4], bl[4];
            ldm4(ah, sb + SQH + ao);
            ldm4(al, sb + SQL + ao);
            ldm4(bh, kb + bo);
            ldm4(bl, kb + 16384 + bo);
#pragma unroll
            for (int hh = 0; hh < 2; hh++) mma16816(sacc[hh], ah, bh[hh], bh[hh + 2]);
#pragma unroll
            for (int hh = 0; hh < 2; hh++) mma16816(sacc[hh], ah, bl[hh], bl[hh + 2]);
#pragma unroll
            for (int hh = 0; hh < 2; hh++) mma16816(sacc[hh], al, bh[hh], bh[hh + 2]);
        }

        // ---- softcap + mask + exp; write P hi/lo; partial row sums ----
        float rs0 = 0.f, rs1 = 0.f;
#pragma unroll
        for (int hh = 0; hh < 2; hh++) {
            int colL = wh * 16 + hh * 8 + 2 * qc;
            int colG = s0 + colL;
            float p00 = capexp(sacc[hh][0], myp0, colG);
            float p01 = capexp(sacc[hh][1], myp0, colG + 1);
            float p10 = capexp(sacc[hh][2], myp1, colG);
            float p11 = capexp(sacc[hh][3], myp1, colG + 1);
            rs0 += p00 + p01;
            rs1 += p10 + p11;
            __nv_bfloat162 lo0, lo1;
            __nv_bfloat162 hi0 = split_pack_hi(p00, p01, &lo0);
            __nv_bfloat162 hi1 = split_pack_hi(p10, p11, &lo1);
            int r0 = wm * 16 + qr;
            uint32_t o0 = (uint32_t)(r0 * 80 + colL * 2);
            uint32_t o1 = o0 + 8 * 80;
            *(__nv_bfloat162*)(sm + SPH + o0) = hi0;
            *(__nv_bfloat162*)(sm + SPL + o0) = lo0;
            *(__nv_bfloat162*)(sm + SPH + o1) = hi1;
            *(__nv_bfloat162*)(sm + SPL + o1) = lo1;
        }
        rs0 += __shfl_xor_sync(0xffffffffu, rs0, 1);
        rs0 += __shfl_xor_sync(0xffffffffu, rs0, 2);
        rs1 += __shfl_xor_sync(0xffffffffu, rs1, 1);
        rs1 += __shfl_xor_sync(0xffffffffu, rs1, 2);
        if (qc == 0) {
            psum[wh * 64 + wm * 16 + qr]     += rs0;
            psum[wh * 64 + wm * 16 + qr + 8] += rs1;
        }
        __syncthreads();

        // ---- P @ V : m16 x d128 per warp, k = 32 ----
        const int prow = wm * 16 + lrow;
#pragma unroll
        for (int ks2 = 0; ks2 < 2; ks2++) {
            uint32_t po = (uint32_t)(prow * 80 + ((ks2 * 2 + lkc) << 4));
            uint32_t ph[4], pl[4];
            ldm4(ph, sb + SPH + po);
            ldm4(pl, sb + SPL + po);
            uint32_t vh4[8][4], vl4[8][4];
#pragma unroll
            for (int nt = 0; nt < 8; nt++) {
                int vrow = wh * 128 + nt * 16 + lrow;
                uint32_t vo = (uint32_t)(vrow * 80 + ((ks2 * 2 + lkc) << 4));
                ldm4(vh4[nt], vb + vo);
                ldm4(vl4[nt], vb + 20480 + vo);
            }
#pragma unroll
            for (int nt = 0; nt < 8; nt++)
#pragma unroll
                for (int hh = 0; hh < 2; hh++)
                    mma16816(oacc[nt * 2 + hh], ph, vh4[nt][hh], vh4[nt][hh + 2]);
#pragma unroll
            for (int nt = 0; nt < 8; nt++)
#pragma unroll
                for (int hh = 0; hh < 2; hh++)
                    mma16816(oacc[nt * 2 + hh], ph, vl4[nt][hh], vl4[nt][hh + 2]);
#pragma unroll
            for (int nt = 0; nt < 8; nt++)
#pragma unroll
                for (int hh = 0; hh < 2; hh++)
                    mma16816(oacc[nt * 2 + hh], pl, vh4[nt][hh], vh4[nt][hh + 2]);
        }
    }

    // ---- epilogue: divide by row sums, write fp16 hi/lo for O-proj ----
    const int r0 = wm * 16 + qr;
    const float inv0 = __fdividef(1.0f, psum[r0] + psum[64 + r0]);
    const float inv1 = __fdividef(1.0f, psum[r0 + 8] + psum[64 + r0 + 8]);
    const size_t tok0 = (size_t)(b * TT + t0 + r0);
#pragma unroll
    for (int nt = 0; nt < 8; nt++) {
#pragma unroll
        for (int hh = 0; hh < 2; hh++) {
            int col = head * HD + wh * 128 + nt * 16 + hh * 8 + 2 * qc;
            float* d = oacc[nt * 2 + hh];
            __half2 lo0, lo1;
            __half2 hi0 = split_pack_hi_h(d[0] * inv0, d[1] * inv0, &lo0);
            __half2 hi1 = split_pack_hi_h(d[2] * inv1, d[3] * inv1, &lo1);
            *(__half2*)(g_ahi + tok0 * 2048 + col)       = hi0;
            *(__half2*)(g_alo + tok0 * 2048 + col)       = lo0;
            *(__half2*)(g_ahi + (tok0 + 8) * 2048 + col) = hi1;
            *(__half2*)(g_alo + (tok0 + 8) * 2048 + col) = lo1;
        }
    }
}

// ============================================================
// Launch (profiler captures launch index 3 -> QKV GEMM fp16x2)
//   0: convert_split_h(x)   1: transpose_h(wq)   2: transpose_h2(wk,wv)
//   3: QKV GEMM  <- profiled   4: rope_table   5: transpose_h(wo)
//   6: normrope   7: vtrans   8: attn   9: O GEMM (fp16 x2)
// ============================================================
extern "C" void kernel_launch(void* const* d_in, const int* in_sizes, int n_in,
                              void* d_out, int out_size)
{
    const float* x      = (const float*)d_in[0];
    const int*   segpos = (const int*)  d_in[1];
    const int*   curind = (const int*)  d_in[2];
    const float* wq     = (const float*)d_in[3];
    const float* wk     = (const float*)d_in[4];
    const float* wv     = (const float*)d_in[5];
    const float* wo     = (const float*)d_in[6];
    const float* qns    = (const float*)d_in[7];
    const float* kns    = (const float*)d_in[8];
    float* out = (float*)d_out;

    float* gqkv;
    __half *xhi, *xlo, *ahi, *alo, *wqkv, *wohi;
    cudaGetSymbolAddress((void**)&gqkv, g_qkv);
    cudaGetSymbolAddress((void**)&xhi,  g_xhi);
    cudaGetSymbolAddress((void**)&xlo,  g_xlo);
    cudaGetSymbolAddress((void**)&ahi,  g_ahi);
    cudaGetSymbolAddress((void**)&alo,  g_alo);
    cudaGetSymbolAddress((void**)&wqkv, g_wqkv);
    cudaGetSymbolAddress((void**)&wohi, g_wohi);

    cudaFuncSetAttribute(gemm_fp16x2, cudaFuncAttributeMaxDynamicSharedMemorySize, GEMMH_SMEM);
    cudaFuncSetAttribute(attn_mma, cudaFuncAttributeMaxDynamicSharedMemorySize, ATTN_SMEM);

    // 0) split x into fp16 hi/lo
    {
        int n4 = (MM * DD) / 4;
        convert_split_h<<<n4 / 256, 256>>>((const float4*)x,
                                           (__half2*)xhi, (__half2*)xlo, n4);
    }
    // 1-2) transpose q/k/v weights to fp16 [N,K]
    transpose_h<<<dim3(DD / 32, DD / 32), dim3(32, 8)>>>(wq, wqkv, DD, DD);
    transpose_h2<<<dim3(2 * (NKV * HD) / 32, DD / 32), dim3(32, 8)>>>(
        wk, wv, wqkv + (size_t)2048 * DD, wqkv + (size_t)3072 * DD, DD, NKV * HD);

    // 3) fused QKV projection (fp16 x2)  <- profiled launch
    gemm_fp16x2<<<dim3(4096 / 128, MM / 128), 256, GEMMH_SMEM>>>(
        xhi, xlo, wqkv, gqkv, 4096, DD);

    // 4) rope table ; 5) wo transpose (fp16)
    rope_table<<<(MM * 128) / 256, 256>>>(segpos);
    transpose_h<<<dim3(DD / 32, (NH * HD) / 32), dim3(32, 8)>>>(wo, wohi, NH * HD, DD);

    // 6-7) norm + rope -> bf16 hi/lo q + k-cache ; v transpose -> vt cache
    normrope_kernel<<<dim3(MM, NH + NKV), 256>>>(segpos, curind, qns, kns);
    vtrans_kernel<<<dim3(TT / 32, HD / 32, BB * NKV), dim3(32, 8)>>>(curind);

    // 8) HMMA attention -> g_ahi/g_alo (fp16)
    attn_mma<<<dim3(TT / ATQ, NH, BB), 256, ATTN_SMEM>>>(segpos);

    // 9) output projection (fp16 2-product) -> d_out
    gemm_fp16x2<<<dim3(DD / 128, MM / 128), 256, GEMMH_SMEM>>>(
        ahi, alo, wohi, out, DD, NH * HD);
}

// round 15
// speedup vs baseline: 1.5263x; 1.1034x over previous
#include <cuda_runtime.h>
#include <cuda_bf16.h>
#include <cuda_fp16.h>
#include <math.h>
#include <cstdint>

// ---- problem constants ----
#define BB   2
#define TT   2048
#define DD   2048
#define NH   8
#define NKV  4
#define HD   256
#define SC   2048
#define WIN  512
#define GRP  (NH / NKV)   // 2
#define MM   (BB * TT)    // 4096

// ---- device scratch ----
__device__ float g_qkv[(size_t)MM * 4096];              // fused projection output (fp32)
__device__ float2 g_rope[(size_t)MM * 128];             // per-(row, i) sin/cos

// x split, fp16 hi/lo (A-operand of QKV projection)
__device__ __half g_xhi[(size_t)MM * DD], g_xlo[(size_t)MM * DD];
// attention output, fp16 hi/lo (A-operand of O projection)
__device__ __half g_ahi[(size_t)MM * NH * HD], g_alo[(size_t)MM * NH * HD];

// attention operand caches, fp16: Q hi/lo ; K hi only ; Vt hi only
__device__ __half g_qhi[(size_t)BB * NH * TT * HD], g_qlo[(size_t)BB * NH * TT * HD];
__device__ __half g_khi[(size_t)BB * NKV * SC * HD];
__device__ __half g_vthi[(size_t)BB * NKV * HD * SC];

// weights transposed [N,K], fp16 hi only. rows: wq [0,2048), wk [2048,3072), wv [3072,4096)
__device__ __half g_wqkv[(size_t)4096 * DD];
__device__ __half g_wohi[(size_t)DD * DD];              // wo transposed [N,K], fp16 hi

// ============================================================
// helpers
// ============================================================
__device__ __forceinline__ uint32_t s2u(const void* p) {
    uint32_t a;
    asm("{ .reg .u64 t; cvta.to.shared.u64 t, %1; cvt.u32.u64 %0, t; }" : "=r"(a) : "l"(p));
    return a;
}
__device__ __forceinline__ void cpasync16(uint32_t saddr, const void* gaddr) {
    asm volatile("cp.async.cg.shared.global [%0], [%1], 16;" :: "r"(saddr), "l"(gaddr));
}
__device__ __forceinline__ void cp_commit() {
    asm volatile("cp.async.commit_group;" ::: "memory");
}
__device__ __forceinline__ void cp_wait1() {
    asm volatile("cp.async.wait_group 1;" ::: "memory");
}
__device__ __forceinline__ void cp_wait0() {
    asm volatile("cp.async.wait_group 0;" ::: "memory");
}
__device__ __forceinline__ void ldm4(uint32_t* d, uint32_t addr) {
    asm volatile("ldmatrix.sync.aligned.m8n8.x4.shared.b16 {%0,%1,%2,%3}, [%4];"
                 : "=r"(d[0]), "=r"(d[1]), "=r"(d[2]), "=r"(d[3]) : "r"(addr));
}
__device__ __forceinline__ void mma16816h(float* c, const uint32_t* a, uint32_t b0, uint32_t b1) {
    asm volatile("mma.sync.aligned.m16n8k16.row.col.f32.f16.f16.f32 "
                 "{%0,%1,%2,%3}, {%4,%5,%6,%7}, {%8,%9}, {%0,%1,%2,%3};"
                 : "+f"(c[0]), "+f"(c[1]), "+f"(c[2]), "+f"(c[3])
                 : "r"(a[0]), "r"(a[1]), "r"(a[2]), "r"(a[3]), "r"(b0), "r"(b1));
}
__device__ __forceinline__ __half2 split_pack_hi_h(float a, float b, __half2* lo) {
    __half ha = __float2half_rn(a), hb = __float2half_rn(b);
    *lo = __halves2half2(__float2half_rn(a - __half2float(ha)),
                         __float2half_rn(b - __half2float(hb)));
    return __halves2half2(ha, hb);
}

// ============================================================
// convert: fp32 -> (hi, lo) fp16 pair, vectorized x4
// ============================================================
__global__ void __launch_bounds__(256) convert_split_h(const float4* __restrict__ src,
                                                       __half2* __restrict__ hi,
                                                       __half2* __restrict__ lo,
                                                       int n4)
{
    int i = blockIdx.x * 256 + threadIdx.x;
    if (i >= n4) return;
    float4 v = src[i];
    __half2 l0, l1;
    __half2 h0 = split_pack_hi_h(v.x, v.y, &l0);
    __half2 h1 = split_pack_hi_h(v.z, v.w, &l1);
    hi[2 * i] = h0; hi[2 * i + 1] = h1;
    lo[2 * i] = l0; lo[2 * i + 1] = l1;
}

// ============================================================
// transpose to fp16 (hi only): W[K,N] fp32 -> Wt [N,K] fp16
// ============================================================
__global__ void __launch_bounds__(256) transpose_h(const float* __restrict__ W,
                                                   __half* __restrict__ Th,
                                                   int K, int N)
{
    __shared__ float s[32][33];
    int n0 = blockIdx.x * 32, k0 = blockIdx.y * 32;
    for (int i = threadIdx.y; i < 32; i += 8)
        s[i][threadIdx.x] = W[(size_t)(k0 + i) * N + n0 + threadIdx.x];
    __syncthreads();
    for (int i = threadIdx.y; i < 32; i += 8) {
        size_t o = (size_t)(n0 + i) * K + k0 + threadIdx.x;
        Th[o] = __float2half_rn(s[threadIdx.x][i]);
    }
}

// fused two-tensor variant (wk, wv)
__global__ void __launch_bounds__(256) transpose_h2(const float* __restrict__ Wa,
                                                    const float* __restrict__ Wb,
                                                    __half* __restrict__ Tha,
                                                    __half* __restrict__ Thb,
                                                    int K, int N)
{
    __shared__ float s[32][33];
    const int nb = N / 32;
    const bool second = (blockIdx.x >= nb);
    const float* W = second ? Wb : Wa;
    __half* Th = second ? Thb : Tha;
    int n0 = (second ? blockIdx.x - nb : blockIdx.x) * 32;
    int k0 = blockIdx.y * 32;
    for (int i = threadIdx.y; i < 32; i += 8)
        s[i][threadIdx.x] = W[(size_t)(k0 + i) * N + n0 + threadIdx.x];
    __syncthreads();
    for (int i = threadIdx.y; i < 32; i += 8) {
        size_t o = (size_t)(n0 + i) * K + k0 + threadIdx.x;
        Th[o] = __float2half_rn(s[threadIdx.x][i]);
    }
}

// ============================================================
// RoPE sin/cos table: per (row, i<128)
// ============================================================
__global__ void __launch_bounds__(256) rope_table(const int* __restrict__ segpos)
{
    int idx = blockIdx.x * 256 + threadIdx.x;       // MM*128 total
    int row = idx >> 7, i = idx & 127;
    float pos = (float)segpos[row];
    float ts  = exp2f((float)i * (13.287712379549449f / 128.0f));
    float sv, cv;
    sincosf(pos / ts, &sv, &cv);
    g_rope[idx] = make_float2(sv, cv);
}

// ============================================================
// V transpose: g_qkv v-section -> g_vthi [b][kv][d][s] fp16 hi
// ============================================================
__global__ void __launch_bounds__(256) vtrans_kernel(const int* __restrict__ curind)
{
    __shared__ float s[32][33];
    int t0 = blockIdx.x * 32, d0 = blockIdx.y * 32;
    int bkv = blockIdx.z;
    int b = bkv / NKV, kv = bkv - b * NKV;
    int tx = threadIdx.x, ty = threadIdx.y;
    for (int i = ty; i < 32; i += 8)
        s[i][tx] = g_qkv[(size_t)(b * TT + t0 + i) * 4096 + 3072 + kv * HD + d0 + tx];
    __syncthreads();
    int s0 = curind[0] + t0;
    for (int i = ty; i < 32; i += 8) {
        size_t o = ((size_t)bkv * HD + d0 + i) * SC + s0 + tx;
        g_vthi[o] = __float2half_rn(s[tx][i]);
    }
}

// ============================================================
// HMMA GEMM fp16 x2-product: C = (Ahi+Alo)[M,K] @ Bhi[N,K]^T
// 128x128 CTA tile, BK=64, 2-stage cp.async, 8 warps (4x2),
// warp 32x64, 48KB/stage -> 96KB smem -> 2 CTAs/SM.
// ============================================================
#define H_AHI 0
#define H_ALO 16384
#define H_BHI 32768
#define H_STAGE 49152
#define GEMMH_SMEM (2 * H_STAGE)            // 98304

__device__ __forceinline__ void load_stage_h(uint32_t sbase,
    const __half* __restrict__ Ahi, const __half* __restrict__ Alo,
    const __half* __restrict__ Bhi,
    int Kdim, int m0, int n0, int k0, int tid)
{
#pragma unroll
    for (int ii = 0; ii < 4; ii++) {
        int i = tid + ii * 256;
        int r = i >> 3, c = i & 7;
        uint32_t so = (uint32_t)(r * 128 + ((c ^ (r & 7)) << 4));
        size_t goA = (size_t)(m0 + r) * Kdim + k0 + c * 8;
        size_t goB = (size_t)(n0 + r) * Kdim + k0 + c * 8;
        cpasync16(sbase + H_AHI + so, Ahi + goA);
        cpasync16(sbase + H_ALO + so, Alo + goA);
        cpasync16(sbase + H_BHI + so, Bhi + goB);
    }
}

__global__ void __launch_bounds__(256, 2) gemm_fp16x2(
    const __half* __restrict__ Ahi, const __half* __restrict__ Alo,
    const __half* __restrict__ Bhi,
    float* __restrict__ C, int Ndim, int Kdim)
{
    extern __shared__ __align__(128) char smem[];
    const uint32_t sb = s2u(smem);
    const int tid  = threadIdx.x;
    const int wid  = tid >> 5;
    const int lane = tid & 31;
    const int wm   = wid >> 1;
    const int wn   = wid & 1;
    const int m0   = blockIdx.y * 128;
    const int n0   = blockIdx.x * 128;

    const int lrow = lane & 15;
    const int lkc  = lane >> 4;

    int arow[2], brow[4];
#pragma unroll
    for (int mt = 0; mt < 2; mt++) arow[mt] = wm * 32 + mt * 16 + lrow;
#pragma unroll
    for (int nt = 0; nt < 4; nt++) brow[nt] = wn * 64 + nt * 16 + lrow;

    float acc[2][4][2][4];
#pragma unroll
    for (int mt = 0; mt < 2; mt++)
#pragma unroll
        for (int nt = 0; nt < 4; nt++)
#pragma unroll
            for (int h = 0; h < 2; h++)
#pragma unroll
                for (int r = 0; r < 4; r++) acc[mt][nt][h][r] = 0.f;

    const int nk = Kdim >> 6;

    load_stage_h(sb, Ahi, Alo, Bhi, Kdim, m0, n0, 0, tid);
    cp_commit();

    for (int c = 0; c < nk; c++) {
        if (c + 1 < nk) {
            load_stage_h(sb + ((c + 1) & 1) * H_STAGE, Ahi, Alo, Bhi,
                         Kdim, m0, n0, (c + 1) << 6, tid);
            cp_commit();
            cp_wait1();
        } else {
            cp_wait0();
        }
        __syncthreads();

        const uint32_t st = sb + (c & 1) * H_STAGE;

#pragma unroll
        for (int ks = 0; ks < 4; ks++) {
            const int chunk = ks * 2 + lkc;
            uint32_t ah[2][4], al[2][4], bh[4][4];
#pragma unroll
            for (int mt = 0; mt < 2; mt++) {
                uint32_t off = (uint32_t)(arow[mt] * 128 + ((chunk ^ (arow[mt] & 7)) << 4));
                ldm4(ah[mt], st + H_AHI + off);
                ldm4(al[mt], st + H_ALO + off);
            }
#pragma unroll
            for (int nt = 0; nt < 4; nt++) {
                uint32_t off = (uint32_t)(brow[nt] * 128 + ((chunk ^ (brow[nt] & 7)) << 4));
                ldm4(bh[nt], st + H_BHI + off);
            }
#pragma unroll
            for (int mt = 0; mt < 2; mt++)
#pragma unroll
                for (int nt = 0; nt < 4; nt++)
#pragma unroll
                    for (int h = 0; h < 2; h++)
                        mma16816h(acc[mt][nt][h], ah[mt], bh[nt][h], bh[nt][h + 2]);
#pragma unroll
            for (int mt = 0; mt < 2; mt++)
#pragma unroll
                for (int nt = 0; nt < 4; nt++)
#pragma unroll
                    for (int h = 0; h < 2; h++)
                        mma16816h(acc[mt][nt][h], al[mt], bh[nt][h], bh[nt][h + 2]);
        }
        __syncthreads();
    }

    const int qr = lane >> 2;
    const int qc = lane & 3;
#pragma unroll
    for (int mt = 0; mt < 2; mt++) {
#pragma unroll
        for (int nt = 0; nt < 4; nt++) {
#pragma unroll
            for (int h = 0; h < 2; h++) {
                int row = m0 + wm * 32 + mt * 16 + qr;
                int col = n0 + wn * 64 + nt * 16 + h * 8 + qc * 2;
                float* d = acc[mt][nt][h];
                *(float2*)(C + (size_t)row * Ndim + col)       = make_float2(d[0], d[1]);
                *(float2*)(C + (size_t)(row + 8) * Ndim + col) = make_float2(d[2], d[3]);
            }
        }
    }
}

// ============================================================
// RMSNorm + RoPE (table) -> fp16 operand caches
//   q: hi/lo ; k: hi only
// ============================================================
__global__ void __launch_bounds__(256) normrope_kernel(const int* __restrict__ segpos,
                                                       const int* __restrict__ curind,
                                                       const float* __restrict__ qns,
                                                       const float* __restrict__ kns)
{
    const int row  = blockIdx.x;
    const int slot = blockIdx.y;
    const int d    = threadIdx.x;
    const int b    = row / TT;
    const int t    = row - b * TT;

    const float* src;
    const float* sc;
    if (slot < NH) {
        src = g_qkv + (size_t)row * 4096 + slot * HD;
        sc  = qns;
    } else {
        src = g_qkv + (size_t)row * 4096 + 2048 + (slot - NH) * HD;
        sc  = kns;
    }

    float v  = src[d];
    float ss = v * v;
#pragma unroll
    for (int o = 16; o > 0; o >>= 1) ss += __shfl_xor_sync(0xffffffffu, ss, o);

    __shared__ float wsum[8];
    __shared__ float s_n[HD];
    __shared__ float s_r;
    if ((d & 31) == 0) wsum[d >> 5] = ss;
    __syncthreads();
    if (d == 0) {
        float tot = 0.f;
#pragma unroll
        for (int w = 0; w < 8; w++) tot += wsum[w];
        s_r = rsqrtf(tot * (1.0f / HD) + 1e-6f);
    }
    __syncthreads();

    float n = v * s_r * (1.0f + sc[d]);
    s_n[d] = n;
    __syncthreads();

    float2 sc2 = g_rope[(size_t)row * 128 + (d & 127)];
    float outv = (d < 128) ? (n * sc2.y - s_n[d + 128] * sc2.x)
                           : (n * sc2.y + s_n[d - 128] * sc2.x);

    if (slot < NH) {
        outv *= 0.0625f;   // fold HD^-1/2
        size_t o = ((size_t)(b * NH + slot) * TT + t) * HD + d;
        __half h = __float2half_rn(outv);
        g_qhi[o] = h;
        g_qlo[o] = __float2half_rn(outv - __half2float(h));
    } else {
        int kv = slot - NH;
        int ct = curind[0] + t;
        size_t o = ((size_t)(b * NKV + kv) * SC + ct) * HD + d;
        g_khi[o] = __float2half_rn(outv);
    }
}

// ============================================================
// HMMA windowed attention, fp16 (Q hi/lo, K hi, V hi, P hi).
// Double-buffered K/V chunk pipeline; 64 queries x (b,h); 8 warps.
// ============================================================
#define ATQ 64
#define ACK 32
// smem byte offsets
#define SQH 0                          // Q hi: 4 subtiles x 64 x 128B = 32768
#define SQL 32768
#define SKB0 65536                     // K stage: hi 16384 ; x2 stages
#define SK_STRIDE 16384
#define SVB0 98304                     // V stage: hi 20480 ; x2 stages
#define SV_STRIDE 20480
#define SPH 139264                     // P hi: 64 x 80B = 5120
#define SPS 144384                     // psum[2][64] fp32 = 512
#define ATTN_SMEM 144896

__device__ __forceinline__ float capexp(float a, int pos, int s) {
    float e = __expf(a * 0.04f);                       // e^{2a/50}
    float t = 50.0f * __fdividef(e - 1.0f, e + 1.0f);  // 50*tanh(a/50)
    bool valid = (s <= pos) && (pos - s < WIN);
    return valid ? __expf(t) : 0.0f;
}

__device__ __forceinline__ void attn_load_chunk(char* sm, uint32_t sb, int buf,
                                                int s0, int bkv, int tid)
{
    const uint32_t kb = sb + SKB0 + buf * SK_STRIDE;
    const uint32_t ko = SKB0 + buf * SK_STRIDE;
    for (int i = tid; i < 32 * 32; i += 256) {
        int r = i >> 5, c = i & 31;
        int s = s0 + r;
        int sub = c >> 3, cc = c & 7;
        uint32_t so = (uint32_t)(sub * 4096 + r * 128 + ((cc ^ (r & 7)) << 4));
        if (s < SC) {
            size_t go = ((size_t)bkv * SC + s) * HD + c * 8;
            cpasync16(kb + so, g_khi + go);
        } else {
            *(uint4*)(sm + ko + so) = make_uint4(0, 0, 0, 0);
        }
    }
    const uint32_t vb = sb + SVB0 + buf * SV_STRIDE;
    const uint32_t vo = SVB0 + buf * SV_STRIDE;
    for (int i = tid; i < 256 * 4; i += 256) {
        int dd = i >> 2, c = i & 3;
        uint32_t so = (uint32_t)(dd * 80 + c * 16);
        if (s0 + c * 8 + 7 < SC) {
            size_t go = ((size_t)bkv * HD + dd) * SC + s0 + c * 8;
            cpasync16(vb + so, g_vthi + go);
        } else {
            *(uint4*)(sm + vo + so) = make_uint4(0, 0, 0, 0);
        }
    }
}

__global__ void __launch_bounds__(256) attn_mma(const int* __restrict__ segpos)
{
    extern __shared__ __align__(128) char sm[];
    const uint32_t sb = s2u(sm);
    const int tid  = threadIdx.x;
    const int wid  = tid >> 5;
    const int lane = tid & 31;
    const int t0   = blockIdx.x * ATQ;
    const int head = blockIdx.y;
    const int b    = blockIdx.z;
    const int kv   = head / GRP;
    const int bkv  = b * NKV + kv;
    const int wm   = wid >> 1;
    const int wh   = wid & 1;
    const int lrow = lane & 15;
    const int lkc  = lane >> 4;
    const int qr   = lane >> 2;
    const int qc   = lane & 3;

    float* psum = (float*)(sm + SPS);

    int minp, maxp;
    {
        const int* sp = segpos + b * TT + t0;
        minp = sp[0]; maxp = sp[0];
#pragma unroll 8
        for (int i = 1; i < ATQ; i++) {
            int p = sp[i];
            minp = min(minp, p);
            maxp = max(maxp, p);
        }
    }
    const int smin = max(0, minp - (WIN - 1)) & ~31;
    const int smax = min(SC - 1, maxp);
    const int nchunks = ((smax - smin) >> 5) + 1;

    const int myp0 = segpos[b * TT + t0 + wm * 16 + qr];
    const int myp1 = segpos[b * TT + t0 + wm * 16 + qr + 8];

    if (tid < 2 * ATQ) psum[tid] = 0.f;

    // prologue: Q tile + chunk 0  (one commit group)
    {
        const __half* gh = g_qhi + ((size_t)(b * NH + head) * TT + t0) * HD;
        const __half* gl = g_qlo + ((size_t)(b * NH + head) * TT + t0) * HD;
        for (int i = tid; i < ATQ * 32; i += 256) {
            int r = i >> 5, c = i & 31;
            int sub = c >> 3, cc = c & 7;
            uint32_t so = (uint32_t)(sub * 8192 + r * 128 + ((cc ^ (r & 7)) << 4));
            cpasync16(sb + SQH + so, gh + (size_t)r * HD + c * 8);
            cpasync16(sb + SQL + so, gl + (size_t)r * HD + c * 8);
        }
        attn_load_chunk(sm, sb, 0, smin, bkv, tid);
    }
    cp_commit();

    float oacc[16][4];
#pragma unroll
    for (int i = 0; i < 16; i++)
#pragma unroll
        for (int r = 0; r < 4; r++) oacc[i][r] = 0.f;

    for (int ci = 0; ci < nchunks; ci++) {
        const int s0 = smin + ci * ACK;
        __syncthreads();
        if (ci + 1 < nchunks)
            attn_load_chunk(sm, sb, (ci + 1) & 1, s0 + ACK, bkv, tid);
        cp_commit();
        cp_wait1();
        __syncthreads();

        const uint32_t kb = sb + SKB0 + (ci & 1) * SK_STRIDE;
        const uint32_t vb = sb + SVB0 + (ci & 1) * SV_STRIDE;

        // ---- QK^T : m16 x n16 per warp, k = 256, 2 terms ----
        float sacc[2][4];
#pragma unroll
        for (int hh = 0; hh < 2; hh++)
#pragma unroll
            for (int r = 0; r < 4; r++) sacc[hh][r] = 0.f;

        const int arow = wm * 16 + lrow;
        const int brow = wh * 16 + lrow;
#pragma unroll
        for (int ks = 0; ks < 16; ks++) {
            int sub = ks >> 2, cc = (ks & 3) * 2 + lkc;
            uint32_t ao = (uint32_t)(sub * 8192 + arow * 128 + ((cc ^ (arow & 7)) << 4));
            uint32_t bo = (uint32_t)(sub * 4096 + brow * 128 + ((cc ^ (brow & 7)) << 4));
            uint32_t ah[4], al[4], bh[4];
            ldm4(ah, sb + SQH + ao);
            ldm4(al, sb + SQL + ao);
            ldm4(bh, kb + bo);
#pragma unroll
            for (int hh = 0; hh < 2; hh++) mma16816h(sacc[hh], ah, bh[hh], bh[hh + 2]);
#pragma unroll
            for (int hh = 0; hh < 2; hh++) mma16816h(sacc[hh], al, bh[hh], bh[hh + 2]);
        }

        // ---- softcap + mask + exp; write P hi (fp16); partial row sums ----
        float rs0 = 0.f, rs1 = 0.f;
#pragma unroll
        for (int hh = 0; hh < 2; hh++) {
            int colL = wh * 16 + hh * 8 + 2 * qc;
            int colG = s0 + colL;
            float p00 = capexp(sacc[hh][0], myp0, colG);
            float p01 = capexp(sacc[hh][1], myp0, colG + 1);
            float p10 = capexp(sacc[hh][2], myp1, colG);
            float p11 = capexp(sacc[hh][3], myp1, colG + 1);
            rs0 += p00 + p01;
            rs1 += p10 + p11;
            int r0 = wm * 16 + qr;
            uint32_t o0 = (uint32_t)(r0 * 80 + colL * 2);
            uint32_t o1 = o0 + 8 * 80;
            *(__half2*)(sm + SPH + o0) = __halves2half2(__float2half_rn(p00),
                                                        __float2half_rn(p01));
            *(__half2*)(sm + SPH + o1) = __halves2half2(__float2half_rn(p10),
                                                        __float2half_rn(p11));
        }
        rs0 += __shfl_xor_sync(0xffffffffu, rs0, 1);
        rs0 += __shfl_xor_sync(0xffffffffu, rs0, 2);
        rs1 += __shfl_xor_sync(0xffffffffu, rs1, 1);
        rs1 += __shfl_xor_sync(0xffffffffu, rs1, 2);
        if (qc == 0) {
            psum[wh * 64 + wm * 16 + qr]     += rs0;
            psum[wh * 64 + wm * 16 + qr + 8] += rs1;
        }
        __syncthreads();

        // ---- P @ V : m16 x d128 per warp, k = 32, single term ----
        const int prow = wm * 16 + lrow;
#pragma unroll
        for (int ks2 = 0; ks2 < 2; ks2++) {
            uint32_t po = (uint32_t)(prow * 80 + ((ks2 * 2 + lkc) << 4));
            uint32_t ph[4];
            ldm4(ph, sb + SPH + po);
            uint32_t vh4[8][4];
#pragma unroll
            for (int nt = 0; nt < 8; nt++) {
                int vrow = wh * 128 + nt * 16 + lrow;
                uint32_t vo = (uint32_t)(vrow * 80 + ((ks2 * 2 + lkc) << 4));
                ldm4(vh4[nt], vb + vo);
            }
#pragma unroll
            for (int nt = 0; nt < 8; nt++)
#pragma unroll
                for (int hh = 0; hh < 2; hh++)
                    mma16816h(oacc[nt * 2 + hh], ph, vh4[nt][hh], vh4[nt][hh + 2]);
        }
    }

    // ---- epilogue: divide by row sums, write fp16 hi/lo for O-proj ----
    const int r0 = wm * 16 + qr;
    const float inv0 = __fdividef(1.0f, psum[r0] + psum[64 + r0]);
    const float inv1 = __fdividef(1.0f, psum[r0 + 8] + psum[64 + r0 + 8]);
    const size_t tok0 = (size_t)(b * TT + t0 + r0);
#pragma unroll
    for (int nt = 0; nt < 8; nt++) {
#pragma unroll
        for (int hh = 0; hh < 2; hh++) {
            int col = head * HD + wh * 128 + nt * 16 + hh * 8 + 2 * qc;
            float* d = oacc[nt * 2 + hh];
            __half2 lo0, lo1;
            __half2 hi0 = split_pack_hi_h(d[0] * inv0, d[1] * inv0, &lo0);
            __half2 hi1 = split_pack_hi_h(d[2] * inv1, d[3] * inv1, &lo1);
            *(__half2*)(g_ahi + tok0 * 2048 + col)       = hi0;
            *(__half2*)(g_alo + tok0 * 2048 + col)       = lo0;
            *(__half2*)(g_ahi + (tok0 + 8) * 2048 + col) = hi1;
            *(__half2*)(g_alo + (tok0 + 8) * 2048 + col) = lo1;
        }
    }
}

// ============================================================
// Launch (profiler captures launch index 3 -> QKV GEMM fp16x2)
//   0: convert_split_h(x)   1: transpose_h(wq)   2: transpose_h2(wk,wv)
//   3: QKV GEMM  <- profiled   4: rope_table   5: transpose_h(wo)
//   6: normrope   7: vtrans   8: attn   9: O GEMM (fp16 x2)
// ============================================================
extern "C" void kernel_launch(void* const* d_in, const int* in_sizes, int n_in,
                              void* d_out, int out_size)
{
    const float* x      = (const float*)d_in[0];
    const int*   segpos = (const int*)  d_in[1];
    const int*   curind = (const int*)  d_in[2];
    const float* wq     = (const float*)d_in[3];
    const float* wk     = (const float*)d_in[4];
    const float* wv     = (const float*)d_in[5];
    const float* wo     = (const float*)d_in[6];
    const float* qns    = (const float*)d_in[7];
    const float* kns    = (const float*)d_in[8];
    float* out = (float*)d_out;

    float* gqkv;
    __half *xhi, *xlo, *ahi, *alo, *wqkv, *wohi;
    cudaGetSymbolAddress((void**)&gqkv, g_qkv);
    cudaGetSymbolAddress((void**)&xhi,  g_xhi);
    cudaGetSymbolAddress((void**)&xlo,  g_xlo);
    cudaGetSymbolAddress((void**)&ahi,  g_ahi);
    cudaGetSymbolAddress((void**)&alo,  g_alo);
    cudaGetSymbolAddress((void**)&wqkv, g_wqkv);
    cudaGetSymbolAddress((void**)&wohi, g_wohi);

    cudaFuncSetAttribute(gemm_fp16x2, cudaFuncAttributeMaxDynamicSharedMemorySize, GEMMH_SMEM);
    cudaFuncSetAttribute(attn_mma, cudaFuncAttributeMaxDynamicSharedMemorySize, ATTN_SMEM);

    // 0) split x into fp16 hi/lo
    {
        int n4 = (MM * DD) / 4;
        convert_split_h<<<n4 / 256, 256>>>((const float4*)x,
                                           (__half2*)xhi, (__half2*)xlo, n4);
    }
    // 1-2) transpose q/k/v weights to fp16 [N,K]
    transpose_h<<<dim3(DD / 32, DD / 32), dim3(32, 8)>>>(wq, wqkv, DD, DD);
    transpose_h2<<<dim3(2 * (NKV * HD) / 32, DD / 32), dim3(32, 8)>>>(
        wk, wv, wqkv + (size_t)2048 * DD, wqkv + (size_t)3072 * DD, DD, NKV * HD);

    // 3) fused QKV projection (fp16 x2)  <- profiled launch
    gemm_fp16x2<<<dim3(4096 / 128, MM / 128), 256, GEMMH_SMEM>>>(
        xhi, xlo, wqkv, gqkv, 4096, DD);

    // 4) rope table ; 5) wo transpose (fp16)
    rope_table<<<(MM * 128) / 256, 256>>>(segpos);
    transpose_h<<<dim3(DD / 32, (NH * HD) / 32), dim3(32, 8)>>>(wo, wohi, NH * HD, DD);

    // 6-7) norm + rope -> fp16 q hi/lo + k hi cache ; v transpose -> vt hi cache
    normrope_kernel<<<dim3(MM, NH + NKV), 256>>>(segpos, curind, qns, kns);
    vtrans_kernel<<<dim3(TT / 32, HD / 32, BB * NKV), dim3(32, 8)>>>(curind);

    // 8) HMMA attention (fp16) -> g_ahi/g_alo
    attn_mma<<<dim3(TT / ATQ, NH, BB), 256, ATTN_SMEM>>>(segpos);

    // 9) output projection (fp16 2-product) -> d_out
    gemm_fp16x2<<<dim3(DD / 128, MM / 128), 256, GEMMH_SMEM>>>(
        ahi, alo, wohi, out, DD, NH * HD);
}

// round 16
// speedup vs baseline: 1.6476x; 1.0794x over previous
#include <cuda_runtime.h>
#include <cuda_bf16.h>
#include <cuda_fp16.h>
#include <math.h>
#include <cstdint>

// ---- problem constants ----
#define BB   2
#define TT   2048
#define DD   2048
#define NH   8
#define NKV  4
#define HD   256
#define SC   2048
#define WIN  512
#define GRP  (NH / NKV)   // 2
#define MM   (BB * TT)    // 4096

// ---- device scratch ----
__device__ float g_qkv[(size_t)MM * 4096];              // fused projection output (fp32)
__device__ float2 g_rope[(size_t)MM * 128];             // per-(row, i) sin/cos

// x split, fp16 hi/lo (A-operand of QKV projection)
__device__ __half g_xhi[(size_t)MM * DD], g_xlo[(size_t)MM * DD];
// attention output, fp16 hi/lo (A-operand of O projection)
__device__ __half g_ahi[(size_t)MM * NH * HD], g_alo[(size_t)MM * NH * HD];

// attention operand caches, fp16: Q hi/lo ; K hi only ; Vt hi only
__device__ __half g_qhi[(size_t)BB * NH * TT * HD], g_qlo[(size_t)BB * NH * TT * HD];
__device__ __half g_khi[(size_t)BB * NKV * SC * HD];
__device__ __half g_vthi[(size_t)BB * NKV * HD * SC];

// weights transposed [N,K], fp16 hi only. rows: wq [0,2048), wk [2048,3072), wv [3072,4096)
__device__ __half g_wqkv[(size_t)4096 * DD];
__device__ __half g_wohi[(size_t)DD * DD];              // wo transposed [N,K], fp16 hi

// ============================================================
// helpers
// ============================================================
__device__ __forceinline__ uint32_t s2u(const void* p) {
    uint32_t a;
    asm("{ .reg .u64 t; cvta.to.shared.u64 t, %1; cvt.u32.u64 %0, t; }" : "=r"(a) : "l"(p));
    return a;
}
__device__ __forceinline__ void cpasync16(uint32_t saddr, const void* gaddr) {
    asm volatile("cp.async.cg.shared.global [%0], [%1], 16;" :: "r"(saddr), "l"(gaddr));
}
__device__ __forceinline__ void cp_commit() {
    asm volatile("cp.async.commit_group;" ::: "memory");
}
__device__ __forceinline__ void cp_wait1() {
    asm volatile("cp.async.wait_group 1;" ::: "memory");
}
__device__ __forceinline__ void cp_wait0() {
    asm volatile("cp.async.wait_group 0;" ::: "memory");
}
__device__ __forceinline__ void ldm4(uint32_t* d, uint32_t addr) {
    asm volatile("ldmatrix.sync.aligned.m8n8.x4.shared.b16 {%0,%1,%2,%3}, [%4];"
                 : "=r"(d[0]), "=r"(d[1]), "=r"(d[2]), "=r"(d[3]) : "r"(addr));
}
__device__ __forceinline__ void mma16816h(float* c, const uint32_t* a, uint32_t b0, uint32_t b1) {
    asm volatile("mma.sync.aligned.m16n8k16.row.col.f32.f16.f16.f32 "
                 "{%0,%1,%2,%3}, {%4,%5,%6,%7}, {%8,%9}, {%0,%1,%2,%3};"
                 : "+f"(c[0]), "+f"(c[1]), "+f"(c[2]), "+f"(c[3])
                 : "r"(a[0]), "r"(a[1]), "r"(a[2]), "r"(a[3]), "r"(b0), "r"(b1));
}
__device__ __forceinline__ __half2 split_pack_hi_h(float a, float b, __half2* lo) {
    __half ha = __float2half_rn(a), hb = __float2half_rn(b);
    *lo = __halves2half2(__float2half_rn(a - __half2float(ha)),
                         __float2half_rn(b - __half2float(hb)));
    return __halves2half2(ha, hb);
}

// ============================================================
// convert: fp32 -> (hi, lo) fp16 pair, vectorized x4
// ============================================================
__global__ void __launch_bounds__(256) convert_split_h(const float4* __restrict__ src,
                                                       __half2* __restrict__ hi,
                                                       __half2* __restrict__ lo,
                                                       int n4)
{
    int i = blockIdx.x * 256 + threadIdx.x;
    if (i >= n4) return;
    float4 v = src[i];
    __half2 l0, l1;
    __half2 h0 = split_pack_hi_h(v.x, v.y, &l0);
    __half2 h1 = split_pack_hi_h(v.z, v.w, &l1);
    hi[2 * i] = h0; hi[2 * i + 1] = h1;
    lo[2 * i] = l0; lo[2 * i + 1] = l1;
}

// ============================================================
// transpose to fp16 (hi only): W[K,N] fp32 -> Wt [N,K] fp16
// ============================================================
__global__ void __launch_bounds__(256) transpose_h(const float* __restrict__ W,
                                                   __half* __restrict__ Th,
                                                   int K, int N)
{
    __shared__ float s[32][33];
    int n0 = blockIdx.x * 32, k0 = blockIdx.y * 32;
    for (int i = threadIdx.y; i < 32; i += 8)
        s[i][threadIdx.x] = W[(size_t)(k0 + i) * N + n0 + threadIdx.x];
    __syncthreads();
    for (int i = threadIdx.y; i < 32; i += 8) {
        size_t o = (size_t)(n0 + i) * K + k0 + threadIdx.x;
        Th[o] = __float2half_rn(s[threadIdx.x][i]);
    }
}

// fused two-tensor variant (wk, wv)
__global__ void __launch_bounds__(256) transpose_h2(const float* __restrict__ Wa,
                                                    const float* __restrict__ Wb,
                                                    __half* __restrict__ Tha,
                                                    __half* __restrict__ Thb,
                                                    int K, int N)
{
    __shared__ float s[32][33];
    const int nb = N / 32;
    const bool second = (blockIdx.x >= nb);
    const float* W = second ? Wb : Wa;
    __half* Th = second ? Thb : Tha;
    int n0 = (second ? blockIdx.x - nb : blockIdx.x) * 32;
    int k0 = blockIdx.y * 32;
    for (int i = threadIdx.y; i < 32; i += 8)
        s[i][threadIdx.x] = W[(size_t)(k0 + i) * N + n0 + threadIdx.x];
    __syncthreads();
    for (int i = threadIdx.y; i < 32; i += 8) {
        size_t o = (size_t)(n0 + i) * K + k0 + threadIdx.x;
        Th[o] = __float2half_rn(s[threadIdx.x][i]);
    }
}

// ============================================================
// RoPE sin/cos table: per (row, i<128)
// ============================================================
__global__ void __launch_bounds__(256) rope_table(const int* __restrict__ segpos)
{
    int idx = blockIdx.x * 256 + threadIdx.x;       // MM*128 total
    int row = idx >> 7, i = idx & 127;
    float pos = (float)segpos[row];
    float ts  = exp2f((float)i * (13.287712379549449f / 128.0f));
    float sv, cv;
    sincosf(pos / ts, &sv, &cv);
    g_rope[idx] = make_float2(sv, cv);
}

// ============================================================
// V transpose: g_qkv v-section -> g_vthi [b][kv][d][s] fp16 hi
// ============================================================
__global__ void __launch_bounds__(256) vtrans_kernel(const int* __restrict__ curind)
{
    __shared__ float s[32][33];
    int t0 = blockIdx.x * 32, d0 = blockIdx.y * 32;
    int bkv = blockIdx.z;
    int b = bkv / NKV, kv = bkv - b * NKV;
    int tx = threadIdx.x, ty = threadIdx.y;
    for (int i = ty; i < 32; i += 8)
        s[i][tx] = g_qkv[(size_t)(b * TT + t0 + i) * 4096 + 3072 + kv * HD + d0 + tx];
    __syncthreads();
    int s0 = curind[0] + t0;
    for (int i = ty; i < 32; i += 8) {
        size_t o = ((size_t)bkv * HD + d0 + i) * SC + s0 + tx;
        g_vthi[o] = __float2half_rn(s[tx][i]);
    }
}

// ============================================================
// HMMA GEMM fp16 x2-product: C = (Ahi+Alo)[M,K] @ Bhi[N,K]^T
// 128x128 CTA tile, BK=64, 2-stage cp.async, 8 warps (4x2),
// warp 32x64, 48KB/stage -> 96KB smem -> 2 CTAs/SM.
// ============================================================
#define H_AHI 0
#define H_ALO 16384
#define H_BHI 32768
#define H_STAGE 49152
#define GEMMH_SMEM (2 * H_STAGE)            // 98304

__device__ __forceinline__ void load_stage_h(uint32_t sbase,
    const __half* __restrict__ Ahi, const __half* __restrict__ Alo,
    const __half* __restrict__ Bhi,
    int Kdim, int m0, int n0, int k0, int tid)
{
#pragma unroll
    for (int ii = 0; ii < 4; ii++) {
        int i = tid + ii * 256;
        int r = i >> 3, c = i & 7;
        uint32_t so = (uint32_t)(r * 128 + ((c ^ (r & 7)) << 4));
        size_t goA = (size_t)(m0 + r) * Kdim + k0 + c * 8;
        size_t goB = (size_t)(n0 + r) * Kdim + k0 + c * 8;
        cpasync16(sbase + H_AHI + so, Ahi + goA);
        cpasync16(sbase + H_ALO + so, Alo + goA);
        cpasync16(sbase + H_BHI + so, Bhi + goB);
    }
}

__global__ void __launch_bounds__(256, 2) gemm_fp16x2(
    const __half* __restrict__ Ahi, const __half* __restrict__ Alo,
    const __half* __restrict__ Bhi,
    float* __restrict__ C, int Ndim, int Kdim)
{
    extern __shared__ __align__(128) char smem[];
    const uint32_t sb = s2u(smem);
    const int tid  = threadIdx.x;
    const int wid  = tid >> 5;
    const int lane = tid & 31;
    const int wm   = wid >> 1;
    const int wn   = wid & 1;
    const int m0   = blockIdx.y * 128;
    const int n0   = blockIdx.x * 128;

    const int lrow = lane & 15;
    const int lkc  = lane >> 4;

    int arow[2], brow[4];
#pragma unroll
    for (int mt = 0; mt < 2; mt++) arow[mt] = wm * 32 + mt * 16 + lrow;
#pragma unroll
    for (int nt = 0; nt < 4; nt++) brow[nt] = wn * 64 + nt * 16 + lrow;

    float acc[2][4][2][4];
#pragma unroll
    for (int mt = 0; mt < 2; mt++)
#pragma unroll
        for (int nt = 0; nt < 4; nt++)
#pragma unroll
            for (int h = 0; h < 2; h++)
#pragma unroll
                for (int r = 0; r < 4; r++) acc[mt][nt][h][r] = 0.f;

    const int nk = Kdim >> 6;

    load_stage_h(sb, Ahi, Alo, Bhi, Kdim, m0, n0, 0, tid);
    cp_commit();

    for (int c = 0; c < nk; c++) {
        if (c + 1 < nk) {
            load_stage_h(sb + ((c + 1) & 1) * H_STAGE, Ahi, Alo, Bhi,
                         Kdim, m0, n0, (c + 1) << 6, tid);
            cp_commit();
            cp_wait1();
        } else {
            cp_wait0();
        }
        __syncthreads();

        const uint32_t st = sb + (c & 1) * H_STAGE;

#pragma unroll
        for (int ks = 0; ks < 4; ks++) {
            const int chunk = ks * 2 + lkc;
            uint32_t ah[2][4], al[2][4], bh[4][4];
#pragma unroll
            for (int mt = 0; mt < 2; mt++) {
                uint32_t off = (uint32_t)(arow[mt] * 128 + ((chunk ^ (arow[mt] & 7)) << 4));
                ldm4(ah[mt], st + H_AHI + off);
                ldm4(al[mt], st + H_ALO + off);
            }
#pragma unroll
            for (int nt = 0; nt < 4; nt++) {
                uint32_t off = (uint32_t)(brow[nt] * 128 + ((chunk ^ (brow[nt] & 7)) << 4));
                ldm4(bh[nt], st + H_BHI + off);
            }
#pragma unroll
            for (int mt = 0; mt < 2; mt++)
#pragma unroll
                for (int nt = 0; nt < 4; nt++)
#pragma unroll
                    for (int h = 0; h < 2; h++)
                        mma16816h(acc[mt][nt][h], ah[mt], bh[nt][h], bh[nt][h + 2]);
#pragma unroll
            for (int mt = 0; mt < 2; mt++)
#pragma unroll
                for (int nt = 0; nt < 4; nt++)
#pragma unroll
                    for (int h = 0; h < 2; h++)
                        mma16816h(acc[mt][nt][h], al[mt], bh[nt][h], bh[nt][h + 2]);
        }
        __syncthreads();
    }

    const int qr = lane >> 2;
    const int qc = lane & 3;
#pragma unroll
    for (int mt = 0; mt < 2; mt++) {
#pragma unroll
        for (int nt = 0; nt < 4; nt++) {
#pragma unroll
            for (int h = 0; h < 2; h++) {
                int row = m0 + wm * 32 + mt * 16 + qr;
                int col = n0 + wn * 64 + nt * 16 + h * 8 + qc * 2;
                float* d = acc[mt][nt][h];
                *(float2*)(C + (size_t)row * Ndim + col)       = make_float2(d[0], d[1]);
                *(float2*)(C + (size_t)(row + 8) * Ndim + col) = make_float2(d[2], d[3]);
            }
        }
    }
}

// ============================================================
// RMSNorm + RoPE (table), warp-per-(row, slot). No barriers, no smem.
// grid = MM*12/8 blocks of 256 threads (8 warps).
// lane holds d = lane*4..+3 and d+128 (RoPE pairs in-lane).
//   slot < NH : q -> g_qhi/g_qlo (scaled 1/16) ; else k -> g_khi
// ============================================================
__global__ void __launch_bounds__(256) normrope_kernel(const int* __restrict__ segpos,
                                                       const int* __restrict__ curind,
                                                       const float* __restrict__ qns,
                                                       const float* __restrict__ kns)
{
    const int gw   = blockIdx.x * 8 + (threadIdx.x >> 5);
    const int lane = threadIdx.x & 31;
    const int row  = gw / 12;
    const int slot = gw - row * 12;
    const int b    = row / TT;
    const int t    = row - b * TT;

    const float* src;
    const float* sc;
    if (slot < NH) {
        src = g_qkv + (size_t)row * 4096 + slot * HD;
        sc  = qns;
    } else {
        src = g_qkv + (size_t)row * 4096 + 2048 + (slot - NH) * HD;
        sc  = kns;
    }

    float4 v0 = *(const float4*)(src + lane * 4);
    float4 v1 = *(const float4*)(src + 128 + lane * 4);
    float ss = v0.x * v0.x + v0.y * v0.y + v0.z * v0.z + v0.w * v0.w
             + v1.x * v1.x + v1.y * v1.y + v1.z * v1.z + v1.w * v1.w;
#pragma unroll
    for (int o = 16; o > 0; o >>= 1) ss += __shfl_xor_sync(0xffffffffu, ss, o);
    const float r = rsqrtf(ss * (1.0f / HD) + 1e-6f);

    float4 s0 = *(const float4*)(sc + lane * 4);
    float4 s1 = *(const float4*)(sc + 128 + lane * 4);

    float n0[4] = { v0.x * r * (1.f + s0.x), v0.y * r * (1.f + s0.y),
                    v0.z * r * (1.f + s0.z), v0.w * r * (1.f + s0.w) };
    float n1[4] = { v1.x * r * (1.f + s1.x), v1.y * r * (1.f + s1.y),
                    v1.z * r * (1.f + s1.z), v1.w * r * (1.f + s1.w) };

    float o0[4], o1[4];
    const float2* rp = g_rope + (size_t)row * 128 + lane * 4;
#pragma unroll
    for (int j = 0; j < 4; j++) {
        float2 f = rp[j];
        o0[j] = n0[j] * f.y - n1[j] * f.x;
        o1[j] = n1[j] * f.y + n0[j] * f.x;
    }

    if (slot < NH) {
        const float s = 0.0625f;   // fold HD^-1/2
        size_t base = ((size_t)(b * NH + slot) * TT + t) * HD + lane * 4;
        __half2 lo;
        __half2 hi;
        hi = split_pack_hi_h(o0[0] * s, o0[1] * s, &lo);
        *(__half2*)(g_qhi + base)     = hi;  *(__half2*)(g_qlo + base)     = lo;
        hi = split_pack_hi_h(o0[2] * s, o0[3] * s, &lo);
        *(__half2*)(g_qhi + base + 2) = hi;  *(__half2*)(g_qlo + base + 2) = lo;
        hi = split_pack_hi_h(o1[0] * s, o1[1] * s, &lo);
        *(__half2*)(g_qhi + base + 128)     = hi;  *(__half2*)(g_qlo + base + 128)     = lo;
        hi = split_pack_hi_h(o1[2] * s, o1[3] * s, &lo);
        *(__half2*)(g_qhi + base + 130)     = hi;  *(__half2*)(g_qlo + base + 130)     = lo;
    } else {
        int kv = slot - NH;
        int ct = curind[0] + t;
        size_t base = ((size_t)(b * NKV + kv) * SC + ct) * HD + lane * 4;
        *(__half2*)(g_khi + base)     = __halves2half2(__float2half_rn(o0[0]), __float2half_rn(o0[1]));
        *(__half2*)(g_khi + base + 2) = __halves2half2(__float2half_rn(o0[2]), __float2half_rn(o0[3]));
        *(__half2*)(g_khi + base + 128) = __halves2half2(__float2half_rn(o1[0]), __float2half_rn(o1[1]));
        *(__half2*)(g_khi + base + 130) = __halves2half2(__float2half_rn(o1[2]), __float2half_rn(o1[3]));
    }
}

// ============================================================
// HMMA windowed attention, fp16 (Q hi/lo, K hi, V hi, P hi).
// Single-buffered K/V chunk (105.5KB smem) -> 2 CTAs/SM overlap.
// 64 queries x (b,h); 8 warps.
// ============================================================
#define ATQ 64
#define ACK 32
// smem byte offsets
#define SQH 0                          // Q hi: 4 subtiles x 64 x 128B = 32768
#define SQL 32768
#define SK  65536                      // K hi: 16384
#define SV  81920                      // Vt hi: 256 x 80B = 20480
#define SPH 102400                     // P hi: 64 x 80B = 5120
#define SPS 107520                     // psum[2][64] fp32 = 512
#define ATTN_SMEM 108032

__device__ __forceinline__ float capexp(float a, int pos, int s) {
    float e = __expf(a * 0.04f);                       // e^{2a/50}
    float t = 50.0f * __fdividef(e - 1.0f, e + 1.0f);  // 50*tanh(a/50)
    bool valid = (s <= pos) && (pos - s < WIN);
    return valid ? __expf(t) : 0.0f;
}

__device__ __forceinline__ void attn_load_chunk(char* sm, uint32_t sb,
                                                int s0, int bkv, int tid)
{
    const uint32_t kb = sb + SK;
    for (int i = tid; i < 32 * 32; i += 256) {
        int r = i >> 5, c = i & 31;
        int s = s0 + r;
        int sub = c >> 3, cc = c & 7;
        uint32_t so = (uint32_t)(sub * 4096 + r * 128 + ((cc ^ (r & 7)) << 4));
        if (s < SC) {
            cpasync16(kb + so, g_khi + ((size_t)bkv * SC + s) * HD + c * 8);
        } else {
            *(uint4*)(sm + SK + so) = make_uint4(0, 0, 0, 0);
        }
    }
    const uint32_t vb = sb + SV;
    for (int i = tid; i < 256 * 4; i += 256) {
        int dd = i >> 2, c = i & 3;
        uint32_t so = (uint32_t)(dd * 80 + c * 16);
        if (s0 + c * 8 + 7 < SC) {
            cpasync16(vb + so, g_vthi + ((size_t)bkv * HD + dd) * SC + s0 + c * 8);
        } else {
            *(uint4*)(sm + SV + so) = make_uint4(0, 0, 0, 0);
        }
    }
}

__global__ void __launch_bounds__(256, 2) attn_mma(const int* __restrict__ segpos)
{
    extern __shared__ __align__(128) char sm[];
    const uint32_t sb = s2u(sm);
    const int tid  = threadIdx.x;
    const int wid  = tid >> 5;
    const int lane = tid & 31;
    const int t0   = blockIdx.x * ATQ;
    const int head = blockIdx.y;
    const int b    = blockIdx.z;
    const int kv   = head / GRP;
    const int bkv  = b * NKV + kv;
    const int wm   = wid >> 1;
    const int wh   = wid & 1;
    const int lrow = lane & 15;
    const int lkc  = lane >> 4;
    const int qr   = lane >> 2;
    const int qc   = lane & 3;

    float* psum = (float*)(sm + SPS);

    int minp, maxp;
    {
        const int* sp = segpos + b * TT + t0;
        minp = sp[0]; maxp = sp[0];
#pragma unroll 8
        for (int i = 1; i < ATQ; i++) {
            int p = sp[i];
            minp = min(minp, p);
            maxp = max(maxp, p);
        }
    }
    const int smin = max(0, minp - (WIN - 1)) & ~31;
    const int smax = min(SC - 1, maxp);
    const int nchunks = ((smax - smin) >> 5) + 1;

    const int myp0 = segpos[b * TT + t0 + wm * 16 + qr];
    const int myp1 = segpos[b * TT + t0 + wm * 16 + qr + 8];

    if (tid < 2 * ATQ) psum[tid] = 0.f;

    // prologue: Q tile + chunk 0  (one commit group)
    {
        const __half* gh = g_qhi + ((size_t)(b * NH + head) * TT + t0) * HD;
        const __half* gl = g_qlo + ((size_t)(b * NH + head) * TT + t0) * HD;
        for (int i = tid; i < ATQ * 32; i += 256) {
            int r = i >> 5, c = i & 31;
            int sub = c >> 3, cc = c & 7;
            uint32_t so = (uint32_t)(sub * 8192 + r * 128 + ((cc ^ (r & 7)) << 4));
            cpasync16(sb + SQH + so, gh + (size_t)r * HD + c * 8);
            cpasync16(sb + SQL + so, gl + (size_t)r * HD + c * 8);
        }
        attn_load_chunk(sm, sb, smin, bkv, tid);
    }
    cp_commit();
    cp_wait0();
    __syncthreads();

    float oacc[16][4];
#pragma unroll
    for (int i = 0; i < 16; i++)
#pragma unroll
        for (int r = 0; r < 4; r++) oacc[i][r] = 0.f;

    for (int ci = 0; ci < nchunks; ci++) {
        const int s0 = smin + ci * ACK;

        // ---- QK^T : m16 x n16 per warp, k = 256, 2 terms ----
        float sacc[2][4];
#pragma unroll
        for (int hh = 0; hh < 2; hh++)
#pragma unroll
            for (int r = 0; r < 4; r++) sacc[hh][r] = 0.f;

        const int arow = wm * 16 + lrow;
        const int brow = wh * 16 + lrow;
#pragma unroll
        for (int ks = 0; ks < 16; ks++) {
            int sub = ks >> 2, cc = (ks & 3) * 2 + lkc;
            uint32_t ao = (uint32_t)(sub * 8192 + arow * 128 + ((cc ^ (arow & 7)) << 4));
            uint32_t bo = (uint32_t)(sub * 4096 + brow * 128 + ((cc ^ (brow & 7)) << 4));
            uint32_t ah[4], al[4], bh[4];
            ldm4(ah, sb + SQH + ao);
            ldm4(al, sb + SQL + ao);
            ldm4(bh, sb + SK + bo);
#pragma unroll
            for (int hh = 0; hh < 2; hh++) mma16816h(sacc[hh], ah, bh[hh], bh[hh + 2]);
#pragma unroll
            for (int hh = 0; hh < 2; hh++) mma16816h(sacc[hh], al, bh[hh], bh[hh + 2]);
        }

        // ---- softcap + mask + exp; write P hi (fp16); partial row sums ----
        float rs0 = 0.f, rs1 = 0.f;
#pragma unroll
        for (int hh = 0; hh < 2; hh++) {
            int colL = wh * 16 + hh * 8 + 2 * qc;
            int colG = s0 + colL;
            float p00 = capexp(sacc[hh][0], myp0, colG);
            float p01 = capexp(sacc[hh][1], myp0, colG + 1);
            float p10 = capexp(sacc[hh][2], myp1, colG);
            float p11 = capexp(sacc[hh][3], myp1, colG + 1);
            rs0 += p00 + p01;
            rs1 += p10 + p11;
            int r0 = wm * 16 + qr;
            uint32_t o0 = (uint32_t)(r0 * 80 + colL * 2);
            uint32_t o1 = o0 + 8 * 80;
            *(__half2*)(sm + SPH + o0) = __halves2half2(__float2half_rn(p00),
                                                        __float2half_rn(p01));
            *(__half2*)(sm + SPH + o1) = __halves2half2(__float2half_rn(p10),
                                                        __float2half_rn(p11));
        }
        rs0 += __shfl_xor_sync(0xffffffffu, rs0, 1);
        rs0 += __shfl_xor_sync(0xffffffffu, rs0, 2);
        rs1 += __shfl_xor_sync(0xffffffffu, rs1, 1);
        rs1 += __shfl_xor_sync(0xffffffffu, rs1, 2);
        if (qc == 0) {
            psum[wh * 64 + wm * 16 + qr]     += rs0;
            psum[wh * 64 + wm * 16 + qr + 8] += rs1;
        }
        __syncthreads();    // P visible; all warps done reading K

        // ---- P @ V : m16 x d128 per warp, k = 32, single term ----
        const int prow = wm * 16 + lrow;
#pragma unroll
        for (int ks2 = 0; ks2 < 2; ks2++) {
            uint32_t po = (uint32_t)(prow * 80 + ((ks2 * 2 + lkc) << 4));
            uint32_t ph[4];
            ldm4(ph, sb + SPH + po);
            uint32_t vh4[8][4];
#pragma unroll
            for (int nt = 0; nt < 8; nt++) {
                int vrow = wh * 128 + nt * 16 + lrow;
                uint32_t vo = (uint32_t)(vrow * 80 + ((ks2 * 2 + lkc) << 4));
                ldm4(vh4[nt], sb + SV + vo);
            }
#pragma unroll
            for (int nt = 0; nt < 8; nt++)
#pragma unroll
                for (int hh = 0; hh < 2; hh++)
                    mma16816h(oacc[nt * 2 + hh], ph, vh4[nt][hh], vh4[nt][hh + 2]);
        }

        // ---- refill the single K/V buffer for next chunk ----
        if (ci + 1 < nchunks) {
            __syncthreads();                        // all warps done with K/V
            attn_load_chunk(sm, sb, s0 + ACK, bkv, tid);
            cp_commit();
            cp_wait0();
            __syncthreads();                        // new chunk visible
        }
    }

    // ---- epilogue: divide by row sums, write fp16 hi/lo for O-proj ----
    const int r0 = wm * 16 + qr;
    const float inv0 = __fdividef(1.0f, psum[r0] + psum[64 + r0]);
    const float inv1 = __fdividef(1.0f, psum[r0 + 8] + psum[64 + r0 + 8]);
    const size_t tok0 = (size_t)(b * TT + t0 + r0);
#pragma unroll
    for (int nt = 0; nt < 8; nt++) {
#pragma unroll
        for (int hh = 0; hh < 2; hh++) {
            int col = head * HD + wh * 128 + nt * 16 + hh * 8 + 2 * qc;
            float* d = oacc[nt * 2 + hh];
            __half2 lo0, lo1;
            __half2 hi0 = split_pack_hi_h(d[0] * inv0, d[1] * inv0, &lo0);
            __half2 hi1 = split_pack_hi_h(d[2] * inv1, d[3] * inv1, &lo1);
            *(__half2*)(g_ahi + tok0 * 2048 + col)       = hi0;
            *(__half2*)(g_alo + tok0 * 2048 + col)       = lo0;
            *(__half2*)(g_ahi + (tok0 + 8) * 2048 + col) = hi1;
            *(__half2*)(g_alo + (tok0 + 8) * 2048 + col) = lo1;
        }
    }
}

// ============================================================
// Launch (profiler captures launch index 3 -> QKV GEMM fp16x2)
//   0: convert_split_h(x)   1: transpose_h(wq)   2: transpose_h2(wk,wv)
//   3: QKV GEMM  <- profiled   4: rope_table   5: transpose_h(wo)
//   6: normrope   7: vtrans   8: attn   9: O GEMM (fp16 x2)
// ============================================================
extern "C" void kernel_launch(void* const* d_in, const int* in_sizes, int n_in,
                              void* d_out, int out_size)
{
    const float* x      = (const float*)d_in[0];
    const int*   segpos = (const int*)  d_in[1];
    const int*   curind = (const int*)  d_in[2];
    const float* wq     = (const float*)d_in[3];
    const float* wk     = (const float*)d_in[4];
    const float* wv     = (const float*)d_in[5];
    const float* wo     = (const float*)d_in[6];
    const float* qns    = (const float*)d_in[7];
    const float* kns    = (const float*)d_in[8];
    float* out = (float*)d_out;

    float* gqkv;
    __half *xhi, *xlo, *ahi, *alo, *wqkv, *wohi;
    cudaGetSymbolAddress((void**)&gqkv, g_qkv);
    cudaGetSymbolAddress((void**)&xhi,  g_xhi);
    cudaGetSymbolAddress((void**)&xlo,  g_xlo);
    cudaGetSymbolAddress((void**)&ahi,  g_ahi);
    cudaGetSymbolAddress((void**)&alo,  g_alo);
    cudaGetSymbolAddress((void**)&wqkv, g_wqkv);
    cudaGetSymbolAddress((void**)&wohi, g_wohi);

    cudaFuncSetAttribute(gemm_fp16x2, cudaFuncAttributeMaxDynamicSharedMemorySize, GEMMH_SMEM);
    cudaFuncSetAttribute(attn_mma, cudaFuncAttributeMaxDynamicSharedMemorySize, ATTN_SMEM);

    // 0) split x into fp16 hi/lo
    {
        int n4 = (MM * DD) / 4;
        convert_split_h<<<n4 / 256, 256>>>((const float4*)x,
                                           (__half2*)xhi, (__half2*)xlo, n4);
    }
    // 1-2) transpose q/k/v weights to fp16 [N,K]
    transpose_h<<<dim3(DD / 32, DD / 32), dim3(32, 8)>>>(wq, wqkv, DD, DD);
    transpose_h2<<<dim3(2 * (NKV * HD) / 32, DD / 32), dim3(32, 8)>>>(
        wk, wv, wqkv + (size_t)2048 * DD, wqkv + (size_t)3072 * DD, DD, NKV * HD);

    // 3) fused QKV projection (fp16 x2)  <- profiled launch
    gemm_fp16x2<<<dim3(4096 / 128, MM / 128), 256, GEMMH_SMEM>>>(
        xhi, xlo, wqkv, gqkv, 4096, DD);

    // 4) rope table ; 5) wo transpose (fp16)
    rope_table<<<(MM * 128) / 256, 256>>>(segpos);
    transpose_h<<<dim3(DD / 32, (NH * HD) / 32), dim3(32, 8)>>>(wo, wohi, NH * HD, DD);

    // 6-7) norm + rope (warp-per-slot) ; v transpose -> vt hi cache
    normrope_kernel<<<(MM * 12) / 8, 256>>>(segpos, curind, qns, kns);
    vtrans_kernel<<<dim3(TT / 32, HD / 32, BB * NKV), dim3(32, 8)>>>(curind);

    // 8) HMMA attention (fp16, 2 CTAs/SM) -> g_ahi/g_alo
    attn_mma<<<dim3(TT / ATQ, NH, BB), 256, ATTN_SMEM>>>(segpos);

    // 9) output projection (fp16 2-product) -> d_out
    gemm_fp16x2<<<dim3(DD / 128, MM / 128), 256, GEMMH_SMEM>>>(
        ahi, alo, wohi, out, DD, NH * HD);
}